// round 6
// baseline (speedup 1.0000x reference)
#include <cuda_runtime.h>
#include <cstdint>

// SNN_Delay: 3x (DCLS gaussian 11-tap temporal conv -> [BN] -> LIF scan), forward only.
// Conv = implicit GEMM, biased FastTwoSum compensated accumulation on packed f32x2.
// R6: f32x2 lanes = row pairs (A loads packed straight from smem), duplicated-B smem
//     (no packing movs at all in the inner loop), block-4 k-fusion on spike layers.

typedef unsigned long long ull;

#define NT 25
#define NB 1024
#define MROWS (NB*NT)          // 25600
#define K1TOT (11*140)         // 1540
#define K2TOT (11*256)         // 2816

__device__ float g_Wg1[K1TOT*256];
__device__ float g_Wg2[K2TOT*256];
__device__ float g_Wg3[K2TOT*32];
__device__ float g_bb1[256];
__device__ float g_bb2[256];
__device__ float g_bb3[32];
__device__ float g_Y[MROWS*256];
__device__ float g_S1[MROWS*256];
__device__ float g_S2[MROWS*256];
__device__ float g_Y3[MROWS*20];

// ---------------------------------------------------------------------------
// Weight prep (fp64 internal): dense DCLS kernel, normalized gaussian taps,
// BN scale folded in. Wg layout: [k = j*I + i][o]  (o contiguous, Ostride cols).
// ---------------------------------------------------------------------------
__global__ void prep_weights(const float* __restrict__ W, const float* __restrict__ P,
                             const float* __restrict__ SIG, const float* __restrict__ gamma,
                             const float* __restrict__ var, float* __restrict__ Wg,
                             int O, int I, int Ostride)
{
    int idx = blockIdx.x * blockDim.x + threadIdx.x;
    if (idx >= O * I) return;
    int o = idx / I;
    int i = idx - o * I;
    double pc = (double)P[idx] + 5.0;          // MAXD//2 = 5
    double s  = fabs((double)SIG[idx]) + 0.27;
    double g[11];
    double sum = 0.0;
#pragma unroll
    for (int j = 0; j < 11; j++) {
        double d = ((double)j - pc) / s;
        g[j] = exp(-0.5 * d * d);
        sum += g[j];
    }
    double scale = (double)W[idx] / (sum + 1e-7);
    if (gamma) scale *= (double)gamma[o] / sqrt((double)var[o] + 1e-5);
#pragma unroll
    for (int j = 0; j < 11; j++)
        Wg[(size_t)(j * I + i) * Ostride + o] = (float)(g[j] * scale);
}

__global__ void zero_buf(float* p, int n)
{
    int i = blockIdx.x * blockDim.x + threadIdx.x;
    if (i < n) p[i] = 0.f;
}

__global__ void prep_bias(const float* __restrict__ b, const float* __restrict__ gamma,
                          const float* __restrict__ beta, const float* __restrict__ mean,
                          const float* __restrict__ var, float* __restrict__ out, int O)
{
    int o = blockIdx.x * blockDim.x + threadIdx.x;
    if (o >= O) return;
    double v = (double)b[o];
    if (gamma) {
        double sc = (double)gamma[o] / sqrt((double)var[o] + 1e-5);
        v = (v - (double)mean[o]) * sc + (double)beta[o];
    }
    out[o] = (float)v;
}

// ---------------------------------------------------------------------------
// packed f32x2 helpers
// ---------------------------------------------------------------------------
__device__ __forceinline__ ull pack2s(float a) {
    ull r; asm("mov.b64 %0, {%1,%1};" : "=l"(r) : "f"(a)); return r;
}
__device__ __forceinline__ void unpack2(ull v, float& x, float& y) {
    asm("mov.b64 {%0,%1}, %2;" : "=f"(x), "=f"(y) : "l"(v));
}
__device__ __forceinline__ ull pmul(ull a, ull b) {
    ull r; asm("mul.rn.f32x2 %0, %1, %2;" : "=l"(r) : "l"(a), "l"(b)); return r;
}
__device__ __forceinline__ ull padd(ull a, ull b) {
    ull r; asm("add.rn.f32x2 %0, %1, %2;" : "=l"(r) : "l"(a), "l"(b)); return r;
}
__device__ __forceinline__ ull pfma(ull a, ull b, ull c) {
    ull r; asm("fma.rn.f32x2 %0, %1, %2, %3;" : "=l"(r) : "l"(a), "l"(b), "l"(c)); return r;
}

#define NEG1_PK  0xBF800000BF800000ULL   // (-1.f, -1.f)
#define CBIAS    512.0f
#define CBIAS_PK 0x4400000044000000ULL   // (512.f, 512.f)

// ---------------------------------------------------------------------------
// Implicit-GEMM conv, biased FastTwoSum accumulation, packed f32x2.
// Lanes of each f32x2 accumulator = two consecutive M rows (same column).
// C[m,n] = sum_k U[m,k]*Wg[k,n] + bias[n],
//   U[m,k] = X[(m-10)*I + k] if k >= (10 - m%25)*I else 0.
// Wg rows stride Nw (padded); Y rows stride N.
// KBLK: number of consecutive k products fused via fma before compensation.
// ---------------------------------------------------------------------------
template<int BM, int BN, int KBLK>
__global__ void __launch_bounds__(256)
conv_gemm_pk(const float* __restrict__ X, const float* __restrict__ Wg,
             const float* __restrict__ bias, float* __restrict__ Y,
             int N, int Nw, int Ktot, int I)
{
    static_assert(BM / 64 * 64 == BM, "BM multiple of 64");
    constexpr int APASS = BM / 64;       // row passes for A loads
    constexpr int CG    = BN / 4;        // col groups
    static_assert(256 / CG * 8 == BM, "compute map covers BM");
    static_assert(16 % KBLK == 0, "KBLK divides 16");
    __shared__ float As[16][BM + 12];    // scalar A; row stride 16B-aligned
    __shared__ ull   Bs2[16][BN + 2];    // duplicated (w,w) pairs; 16B-aligned rows

    const int tid = threadIdx.x;
    const int bm = blockIdx.x * BM;
    const int bn = blockIdx.y * BN;

    // A-load geometry
    const int arow = tid >> 2;          // 0..63
    const int akq  = (tid & 3) * 4;     // 0,4,8,12
    long abase[APASS];
    int  alow[APASS];
#pragma unroll
    for (int r = 0; r < APASS; r++) {
        int m = bm + arow + r * 64;
        int t = m % 25;
        abase[r] = (long)(m - 10) * I;
        alow[r]  = (t < 10) ? (10 - t) * I : 0;   // multiple of 4 (I%4==0)
    }
    // B-load geometry
    const int bkrow = tid / CG;          // k-row
    const int bcq   = (tid % CG) * 4;    // col offset

    ull acc[4][4], cmp[4][4];            // [row-pair][col]
#pragma unroll
    for (int rp = 0; rp < 4; rp++)
#pragma unroll
        for (int c = 0; c < 4; c++) { acc[rp][c] = CBIAS_PK; cmp[rp][c] = 0ull; }

    const int ty = tid / CG;            // 8-row group
    const int tx = tid % CG;            // 4-col group

    for (int k0 = 0; k0 < Ktot; k0 += 16) {
#pragma unroll
        for (int r = 0; r < APASS; r++) {
            int k = k0 + akq;
            float4 v = make_float4(0.f, 0.f, 0.f, 0.f);
            if (k >= alow[r] && k < Ktot)
                v = *reinterpret_cast<const float4*>(X + abase[r] + k);
            int row = arow + r * 64;
            As[akq + 0][row] = v.x;
            As[akq + 1][row] = v.y;
            As[akq + 2][row] = v.z;
            As[akq + 3][row] = v.w;
        }
        if (bkrow < 16) {
            int k = k0 + bkrow;
            float4 v = make_float4(0.f, 0.f, 0.f, 0.f);
            if (k < Ktot)
                v = *reinterpret_cast<const float4*>(Wg + (size_t)k * Nw + bn + bcq);
            Bs2[bkrow][bcq + 0] = pack2s(v.x);
            Bs2[bkrow][bcq + 1] = pack2s(v.y);
            Bs2[bkrow][bcq + 2] = pack2s(v.z);
            Bs2[bkrow][bcq + 3] = pack2s(v.w);
        }
        __syncthreads();

#pragma unroll
        for (int kb = 0; kb < 16; kb += KBLK) {
            ull a[KBLK][4];                        // [kk][row-pair]
#pragma unroll
            for (int kk = 0; kk < KBLK; kk++) {
                ulonglong2 a01 = *reinterpret_cast<const ulonglong2*>(&As[kb + kk][ty * 8]);
                ulonglong2 a23 = *reinterpret_cast<const ulonglong2*>(&As[kb + kk][ty * 8 + 4]);
                a[kk][0] = a01.x; a[kk][1] = a01.y;
                a[kk][2] = a23.x; a[kk][3] = a23.y;
            }
#pragma unroll
            for (int cp = 0; cp < 2; cp++) {       // column pairs (keeps regs low)
                ull b0[KBLK], b1[KBLK];
#pragma unroll
                for (int kk = 0; kk < KBLK; kk++) {
                    ulonglong2 bv = *reinterpret_cast<const ulonglong2*>(
                        &Bs2[kb + kk][tx * 4 + cp * 2]);
                    b0[kk] = bv.x; b1[kk] = bv.y;
                }
#pragma unroll
                for (int rp = 0; rp < 4; rp++) {
#pragma unroll
                    for (int ci = 0; ci < 2; ci++) {
                        int c = cp * 2 + ci;
                        ull pr = pmul(a[0][rp], ci ? b1[0] : b0[0]);
#pragma unroll
                        for (int kk = 1; kk < KBLK; kk++)
                            pr = pfma(a[kk][rp], ci ? b1[kk] : b0[kk], pr);
                        ull s = acc[rp][c];
                        ull t = padd(s, pr);
                        ull d = pfma(s, (ull)NEG1_PK, t);   // t - s  (exact)
                        ull e = pfma(d, (ull)NEG1_PK, pr);  // pr - d (exact)
                        acc[rp][c] = t;
                        cmp[rp][c] = padd(cmp[rp][c], e);
                    }
                }
            }
        }
        __syncthreads();
    }

#pragma unroll
    for (int rp = 0; rp < 4; rp++) {
        int m = bm + ty * 8 + 2 * rp;
#pragma unroll
        for (int c = 0; c < 4; c++) {
            int n = bn + tx * 4 + c;
            if (n < N) {
                float lo, hi, cl, ch;
                unpack2(acc[rp][c], lo, hi);
                unpack2(cmp[rp][c], cl, ch);
                float bsn = bias[n];
                Y[(size_t)m * N + n] =
                    __fadd_rn(__fadd_rn(__fsub_rn(lo, CBIAS), cl), bsn);
                Y[(size_t)(m + 1) * N + n] =
                    __fadd_rn(__fadd_rn(__fsub_rn(hi, CBIAS), ch), bsn);
            }
        }
    }
}

// ---------------------------------------------------------------------------
// LIF scan in fp64 (snntorch Leaky, reset='subtract'). Layout (B,T,C).
// ---------------------------------------------------------------------------
__global__ void lif_kernel(const float* __restrict__ Y, float* __restrict__ S, int C)
{
    int idx = blockIdx.x * blockDim.x + threadIdx.x;
    if (idx >= NB * C) return;
    int b = idx / C;
    int c = idx - b * C;
    const float* y = Y + (size_t)b * NT * C + c;
    float* s = S + (size_t)b * NT * C + c;
    double mem = 0.0;
#pragma unroll
    for (int t = 0; t < NT; t++) {
        double reset = (mem > 1.0) ? 1.0 : 0.0;
        mem = 0.95 * mem + (double)y[t * C] - reset;
        s[t * C] = (mem > 1.0) ? 1.0f : 0.0f;
    }
}

// Final LIF: layer-3 Y row stride 20. Emits spk3 (T,B,20) then mem3 (T,B,20).
__global__ void lif_out_kernel(const float* __restrict__ Y, float* __restrict__ out,
                               int out_size)
{
    int idx = blockIdx.x * blockDim.x + threadIdx.x;
    if (idx >= NB * 20) return;
    int b = idx / 20;
    int c = idx - b * 20;
    bool have_mem = (out_size >= 2 * NT * NB * 20);
    double mem = 0.0;
#pragma unroll
    for (int t = 0; t < NT; t++) {
        double reset = (mem > 1.0) ? 1.0 : 0.0;
        mem = 0.95 * mem + (double)Y[((size_t)b * NT + t) * 20 + c] - reset;
        float spk = (mem > 1.0) ? 1.0f : 0.0f;
        out[(size_t)t * NB * 20 + b * 20 + c] = spk;
        if (have_mem)
            out[(size_t)NT * NB * 20 + (size_t)t * NB * 20 + b * 20 + c] = (float)mem;
    }
}

// ---------------------------------------------------------------------------
extern "C" void kernel_launch(void* const* d_in, const int* in_sizes, int n_in,
                              void* d_out, int out_size)
{
    const float* data = (const float*)d_in[0];
    const float* W1   = (const float*)d_in[1];
    const float* b1   = (const float*)d_in[2];
    const float* P1   = (const float*)d_in[3];
    const float* SIG1 = (const float*)d_in[4];
    const float* g1   = (const float*)d_in[5];
    const float* be1  = (const float*)d_in[6];
    const float* mu1  = (const float*)d_in[7];
    const float* va1  = (const float*)d_in[8];
    const float* W2   = (const float*)d_in[9];
    const float* b2   = (const float*)d_in[10];
    const float* P2   = (const float*)d_in[11];
    const float* SIG2 = (const float*)d_in[12];
    const float* g2   = (const float*)d_in[13];
    const float* be2  = (const float*)d_in[14];
    const float* mu2  = (const float*)d_in[15];
    const float* va2  = (const float*)d_in[16];
    const float* W3   = (const float*)d_in[17];
    const float* b3   = (const float*)d_in[18];
    const float* P3   = (const float*)d_in[19];
    const float* SIG3 = (const float*)d_in[20];

    float *Wg1, *Wg2, *Wg3, *bb1, *bb2, *bb3, *Y, *S1, *S2, *Y3;
    cudaGetSymbolAddress((void**)&Wg1, g_Wg1);
    cudaGetSymbolAddress((void**)&Wg2, g_Wg2);
    cudaGetSymbolAddress((void**)&Wg3, g_Wg3);
    cudaGetSymbolAddress((void**)&bb1, g_bb1);
    cudaGetSymbolAddress((void**)&bb2, g_bb2);
    cudaGetSymbolAddress((void**)&bb3, g_bb3);
    cudaGetSymbolAddress((void**)&Y,   g_Y);
    cudaGetSymbolAddress((void**)&S1,  g_S1);
    cudaGetSymbolAddress((void**)&S2,  g_S2);
    cudaGetSymbolAddress((void**)&Y3,  g_Y3);

    // weight/bias prep (tiny). Layer-3 weights padded to 32 cols (zeros).
    zero_buf<<<(K2TOT * 32 + 255) / 256, 256>>>(Wg3, K2TOT * 32);
    prep_weights<<<(256 * 140 + 255) / 256, 256>>>(W1, P1, SIG1, g1, va1, Wg1, 256, 140, 256);
    prep_weights<<<(256 * 256 + 255) / 256, 256>>>(W2, P2, SIG2, g2, va2, Wg2, 256, 256, 256);
    prep_weights<<<(20 * 256 + 255) / 256, 256>>>(W3, P3, SIG3, nullptr, nullptr, Wg3, 20, 256, 32);
    prep_bias<<<1, 256>>>(b1, g1, be1, mu1, va1, bb1, 256);
    prep_bias<<<1, 256>>>(b2, g2, be2, mu2, va2, bb2, 256);
    prep_bias<<<1, 32>>>(b3, nullptr, nullptr, nullptr, nullptr, bb3, 20);

    // layer 1: dense inputs -> exact per-term compensation (KBLK=1)
    conv_gemm_pk<128, 64, 1><<<dim3(200, 4), 256>>>(data, Wg1, bb1, Y, 256, 256, K1TOT, 140);
    lif_kernel<<<(NB * 256 + 255) / 256, 256>>>(Y, S1, 256);

    // layer 2: spike inputs -> block-4 fused compensation
    conv_gemm_pk<128, 64, 4><<<dim3(200, 4), 256>>>(S1, Wg2, bb2, Y, 256, 256, K2TOT, 256);
    lif_kernel<<<(NB * 256 + 255) / 256, 256>>>(Y, S2, 256);

    // layer 3: spike inputs, N=20 (weight rows padded to 32), no BN
    conv_gemm_pk<256, 32, 4><<<dim3(100, 1), 256>>>(S2, Wg3, bb3, Y3, 20, 32, K2TOT, 256);
    lif_out_kernel<<<(NB * 20 + 255) / 256, 256>>>(Y3, (float*)d_out, out_size);
}

// round 7
// speedup vs baseline: 1.0540x; 1.0540x over previous
#include <cuda_runtime.h>
#include <cstdint>

// SNN_Delay: 3x (DCLS gaussian 11-tap temporal conv -> [BN] -> LIF scan), forward only.
// Conv = implicit GEMM, biased FastTwoSum compensated accumulation on packed f32x2.
// R7: dup-A smem [row][kk] (warp-broadcast reads, zero inner-loop movs),
//     scalar col-pair B (2-phase LDS), KBLK=8 fma product chains on spike layers.

typedef unsigned long long ull;

#define NT 25
#define NB 1024
#define MROWS (NB*NT)          // 25600
#define K1TOT (11*140)         // 1540
#define K2TOT (11*256)         // 2816

__device__ float g_Wg1[K1TOT*256];
__device__ float g_Wg2[K2TOT*256];
__device__ float g_Wg3[K2TOT*32];
__device__ float g_bb1[256];
__device__ float g_bb2[256];
__device__ float g_bb3[32];
__device__ float g_Y[MROWS*256];
__device__ float g_S1[MROWS*256];
__device__ float g_S2[MROWS*256];
__device__ float g_Y3[MROWS*20];

// ---------------------------------------------------------------------------
// Weight prep (fp64 internal): dense DCLS kernel, normalized gaussian taps,
// BN scale folded in. Wg layout: [k = j*I + i][o]  (o contiguous, Ostride cols).
// ---------------------------------------------------------------------------
__global__ void prep_weights(const float* __restrict__ W, const float* __restrict__ P,
                             const float* __restrict__ SIG, const float* __restrict__ gamma,
                             const float* __restrict__ var, float* __restrict__ Wg,
                             int O, int I, int Ostride)
{
    int idx = blockIdx.x * blockDim.x + threadIdx.x;
    if (idx >= O * I) return;
    int o = idx / I;
    int i = idx - o * I;
    double pc = (double)P[idx] + 5.0;          // MAXD//2 = 5
    double s  = fabs((double)SIG[idx]) + 0.27;
    double g[11];
    double sum = 0.0;
#pragma unroll
    for (int j = 0; j < 11; j++) {
        double d = ((double)j - pc) / s;
        g[j] = exp(-0.5 * d * d);
        sum += g[j];
    }
    double scale = (double)W[idx] / (sum + 1e-7);
    if (gamma) scale *= (double)gamma[o] / sqrt((double)var[o] + 1e-5);
#pragma unroll
    for (int j = 0; j < 11; j++)
        Wg[(size_t)(j * I + i) * Ostride + o] = (float)(g[j] * scale);
}

__global__ void zero_buf(float* p, int n)
{
    int i = blockIdx.x * blockDim.x + threadIdx.x;
    if (i < n) p[i] = 0.f;
}

__global__ void prep_bias(const float* __restrict__ b, const float* __restrict__ gamma,
                          const float* __restrict__ beta, const float* __restrict__ mean,
                          const float* __restrict__ var, float* __restrict__ out, int O)
{
    int o = blockIdx.x * blockDim.x + threadIdx.x;
    if (o >= O) return;
    double v = (double)b[o];
    if (gamma) {
        double sc = (double)gamma[o] / sqrt((double)var[o] + 1e-5);
        v = (v - (double)mean[o]) * sc + (double)beta[o];
    }
    out[o] = (float)v;
}

// ---------------------------------------------------------------------------
// packed f32x2 helpers
// ---------------------------------------------------------------------------
__device__ __forceinline__ ull pack2s(float a) {
    ull r; asm("mov.b64 %0, {%1,%1};" : "=l"(r) : "f"(a)); return r;
}
__device__ __forceinline__ void unpack2(ull v, float& x, float& y) {
    asm("mov.b64 {%0,%1}, %2;" : "=f"(x), "=f"(y) : "l"(v));
}
__device__ __forceinline__ ull pmul(ull a, ull b) {
    ull r; asm("mul.rn.f32x2 %0, %1, %2;" : "=l"(r) : "l"(a), "l"(b)); return r;
}
__device__ __forceinline__ ull padd(ull a, ull b) {
    ull r; asm("add.rn.f32x2 %0, %1, %2;" : "=l"(r) : "l"(a), "l"(b)); return r;
}
__device__ __forceinline__ ull pfma(ull a, ull b, ull c) {
    ull r; asm("fma.rn.f32x2 %0, %1, %2, %3;" : "=l"(r) : "l"(a), "l"(b), "l"(c)); return r;
}

#define NEG1_PK  0xBF800000BF800000ULL   // (-1.f, -1.f)
#define CBIAS    512.0f
#define CBIAS_PK 0x4400000044000000ULL   // (512.f, 512.f)

// ---------------------------------------------------------------------------
// Implicit-GEMM conv, biased FastTwoSum accumulation, packed f32x2.
// Accumulator lanes = two adjacent N columns; A broadcast from duplicated smem.
// C[m,n] = sum_k U[m,k]*Wg[k,n] + bias[n],
//   U[m,k] = X[(m-10)*I + k] if k >= (10 - m%25)*I else 0.
// Wg rows stride Nw (padded); Y rows stride N.
// KBLK: consecutive k products chained via fma before one FastTwoSum.
// ---------------------------------------------------------------------------
template<int BM, int BN, int KBLK>
__global__ void __launch_bounds__(256, 1)
conv_gemm_v7(const float* __restrict__ X, const float* __restrict__ Wg,
             const float* __restrict__ bias, float* __restrict__ Y,
             int N, int Nw, int Ktot, int I)
{
    static_assert(BM / 64 * 64 == BM, "BM multiple of 64");
    constexpr int APASS = BM / 64;       // row passes for A loads
    constexpr int CG    = BN / 4;        // col groups
    static_assert(256 / CG * 8 == BM, "compute map covers BM");
    static_assert(16 % KBLK == 0, "KBLK divides 16");
    __shared__ ull   As2[BM][18];        // dup (a,a); [row][kk], stride even -> 16B-aligned pairs
    __shared__ float Bs[16][BN + 4];     // scalar B

    const int tid = threadIdx.x;
    const int bm = blockIdx.x * BM;
    const int bn = blockIdx.y * BN;

    // A-load geometry
    const int arow = tid >> 2;          // 0..63
    const int akq  = (tid & 3) * 4;     // 0,4,8,12
    long abase[APASS];
    int  alow[APASS];
#pragma unroll
    for (int r = 0; r < APASS; r++) {
        int m = bm + arow + r * 64;
        int t = m % 25;
        abase[r] = (long)(m - 10) * I;
        alow[r]  = (t < 10) ? (10 - t) * I : 0;   // multiple of 4 (I%4==0)
    }
    // B-load geometry
    const int bkrow = tid / CG;          // k-row
    const int bcq   = (tid % CG) * 4;    // col offset

    ull acc[8][2], cmp[8][2];            // [row q][col pair]
#pragma unroll
    for (int q = 0; q < 8; q++) {
        acc[q][0] = CBIAS_PK; acc[q][1] = CBIAS_PK;
        cmp[q][0] = 0ull;     cmp[q][1] = 0ull;
    }

    const int ty = tid / CG;            // 8-row group
    const int tx = tid % CG;            // 4-col group

    for (int k0 = 0; k0 < Ktot; k0 += 16) {
#pragma unroll
        for (int r = 0; r < APASS; r++) {
            int k = k0 + akq;
            float4 v = make_float4(0.f, 0.f, 0.f, 0.f);
            if (k >= alow[r] && k < Ktot)
                v = *reinterpret_cast<const float4*>(X + abase[r] + k);
            int row = arow + r * 64;
            ulonglong2 w0; w0.x = pack2s(v.x); w0.y = pack2s(v.y);
            ulonglong2 w1; w1.x = pack2s(v.z); w1.y = pack2s(v.w);
            *reinterpret_cast<ulonglong2*>(&As2[row][akq])     = w0;
            *reinterpret_cast<ulonglong2*>(&As2[row][akq + 2]) = w1;
        }
        if (bkrow < 16) {
            int k = k0 + bkrow;
            float4 v = make_float4(0.f, 0.f, 0.f, 0.f);
            if (k < Ktot)
                v = *reinterpret_cast<const float4*>(Wg + (size_t)k * Nw + bn + bcq);
            *reinterpret_cast<float4*>(&Bs[bkrow][bcq]) = v;
        }
        __syncthreads();

#pragma unroll
        for (int kb = 0; kb < 16; kb += KBLK) {
            // B operands: col pairs as scalar ull (w_n, w_n+1) straight from smem
            ull bq0[KBLK], bq1[KBLK];
#pragma unroll
            for (int kk = 0; kk < KBLK; kk++) {
                ulonglong2 bb = *reinterpret_cast<const ulonglong2*>(&Bs[kb + kk][tx * 4]);
                bq0[kk] = bb.x; bq1[kk] = bb.y;
            }
#pragma unroll
            for (int q = 0; q < 8; q++) {
                // A operands: duplicated pairs, broadcast across the 16 tx lanes
                ull a[KBLK];
                if (KBLK == 1) {
                    a[0] = As2[ty * 8 + q][kb];
                } else {
#pragma unroll
                    for (int kk = 0; kk < KBLK; kk += 2) {
                        ulonglong2 av = *reinterpret_cast<const ulonglong2*>(
                            &As2[ty * 8 + q][kb + kk]);
                        a[kk] = av.x; a[kk + 1] = av.y;
                    }
                }
#pragma unroll
                for (int cp = 0; cp < 2; cp++) {
                    ull pr = pmul(a[0], cp ? bq1[0] : bq0[0]);
#pragma unroll
                    for (int kk = 1; kk < KBLK; kk++)
                        pr = pfma(a[kk], cp ? bq1[kk] : bq0[kk], pr);
                    ull s = acc[q][cp];
                    ull t = padd(s, pr);
                    ull d = pfma(s, (ull)NEG1_PK, t);   // t - s  (exact)
                    ull e = pfma(d, (ull)NEG1_PK, pr);  // pr - d (exact)
                    acc[q][cp] = t;
                    cmp[q][cp] = padd(cmp[q][cp], e);
                }
            }
        }
        __syncthreads();
    }

#pragma unroll
    for (int q = 0; q < 8; q++) {
        int m = bm + ty * 8 + q;
#pragma unroll
        for (int cp = 0; cp < 2; cp++) {
            int n = bn + tx * 4 + cp * 2;
            float t0, t1, c0, c1;
            unpack2(acc[q][cp], t0, t1);
            unpack2(cmp[q][cp], c0, c1);
            if (n < N) {
                float v = __fadd_rn(__fsub_rn(t0, CBIAS), c0);
                Y[(size_t)m * N + n] = __fadd_rn(v, bias[n]);
            }
            if (n + 1 < N) {
                float v = __fadd_rn(__fsub_rn(t1, CBIAS), c1);
                Y[(size_t)m * N + n + 1] = __fadd_rn(v, bias[n + 1]);
            }
        }
    }
}

// ---------------------------------------------------------------------------
// LIF scan in fp64 (snntorch Leaky, reset='subtract'). Layout (B,T,C).
// ---------------------------------------------------------------------------
__global__ void lif_kernel(const float* __restrict__ Y, float* __restrict__ S, int C)
{
    int idx = blockIdx.x * blockDim.x + threadIdx.x;
    if (idx >= NB * C) return;
    int b = idx / C;
    int c = idx - b * C;
    const float* y = Y + (size_t)b * NT * C + c;
    float* s = S + (size_t)b * NT * C + c;
    double mem = 0.0;
#pragma unroll
    for (int t = 0; t < NT; t++) {
        double reset = (mem > 1.0) ? 1.0 : 0.0;
        mem = 0.95 * mem + (double)y[t * C] - reset;
        s[t * C] = (mem > 1.0) ? 1.0f : 0.0f;
    }
}

// Final LIF: layer-3 Y row stride 20. Emits spk3 (T,B,20) then mem3 (T,B,20).
__global__ void lif_out_kernel(const float* __restrict__ Y, float* __restrict__ out,
                               int out_size)
{
    int idx = blockIdx.x * blockDim.x + threadIdx.x;
    if (idx >= NB * 20) return;
    int b = idx / 20;
    int c = idx - b * 20;
    bool have_mem = (out_size >= 2 * NT * NB * 20);
    double mem = 0.0;
#pragma unroll
    for (int t = 0; t < NT; t++) {
        double reset = (mem > 1.0) ? 1.0 : 0.0;
        mem = 0.95 * mem + (double)Y[((size_t)b * NT + t) * 20 + c] - reset;
        float spk = (mem > 1.0) ? 1.0f : 0.0f;
        out[(size_t)t * NB * 20 + b * 20 + c] = spk;
        if (have_mem)
            out[(size_t)NT * NB * 20 + (size_t)t * NB * 20 + b * 20 + c] = (float)mem;
    }
}

// ---------------------------------------------------------------------------
extern "C" void kernel_launch(void* const* d_in, const int* in_sizes, int n_in,
                              void* d_out, int out_size)
{
    const float* data = (const float*)d_in[0];
    const float* W1   = (const float*)d_in[1];
    const float* b1   = (const float*)d_in[2];
    const float* P1   = (const float*)d_in[3];
    const float* SIG1 = (const float*)d_in[4];
    const float* g1   = (const float*)d_in[5];
    const float* be1  = (const float*)d_in[6];
    const float* mu1  = (const float*)d_in[7];
    const float* va1  = (const float*)d_in[8];
    const float* W2   = (const float*)d_in[9];
    const float* b2   = (const float*)d_in[10];
    const float* P2   = (const float*)d_in[11];
    const float* SIG2 = (const float*)d_in[12];
    const float* g2   = (const float*)d_in[13];
    const float* be2  = (const float*)d_in[14];
    const float* mu2  = (const float*)d_in[15];
    const float* va2  = (const float*)d_in[16];
    const float* W3   = (const float*)d_in[17];
    const float* b3   = (const float*)d_in[18];
    const float* P3   = (const float*)d_in[19];
    const float* SIG3 = (const float*)d_in[20];

    float *Wg1, *Wg2, *Wg3, *bb1, *bb2, *bb3, *Y, *S1, *S2, *Y3;
    cudaGetSymbolAddress((void**)&Wg1, g_Wg1);
    cudaGetSymbolAddress((void**)&Wg2, g_Wg2);
    cudaGetSymbolAddress((void**)&Wg3, g_Wg3);
    cudaGetSymbolAddress((void**)&bb1, g_bb1);
    cudaGetSymbolAddress((void**)&bb2, g_bb2);
    cudaGetSymbolAddress((void**)&bb3, g_bb3);
    cudaGetSymbolAddress((void**)&Y,   g_Y);
    cudaGetSymbolAddress((void**)&S1,  g_S1);
    cudaGetSymbolAddress((void**)&S2,  g_S2);
    cudaGetSymbolAddress((void**)&Y3,  g_Y3);

    // weight/bias prep (tiny). Layer-3 weights padded to 32 cols (zeros).
    zero_buf<<<(K2TOT * 32 + 255) / 256, 256>>>(Wg3, K2TOT * 32);
    prep_weights<<<(256 * 140 + 255) / 256, 256>>>(W1, P1, SIG1, g1, va1, Wg1, 256, 140, 256);
    prep_weights<<<(256 * 256 + 255) / 256, 256>>>(W2, P2, SIG2, g2, va2, Wg2, 256, 256, 256);
    prep_weights<<<(20 * 256 + 255) / 256, 256>>>(W3, P3, SIG3, nullptr, nullptr, Wg3, 20, 256, 32);
    prep_bias<<<1, 256>>>(b1, g1, be1, mu1, va1, bb1, 256);
    prep_bias<<<1, 256>>>(b2, g2, be2, mu2, va2, bb2, 256);
    prep_bias<<<1, 32>>>(b3, nullptr, nullptr, nullptr, nullptr, bb3, 20);

    // layer 1: dense inputs -> exact per-term compensation (KBLK=1)
    conv_gemm_v7<128, 64, 1><<<dim3(200, 4), 256>>>(data, Wg1, bb1, Y, 256, 256, K1TOT, 140);
    lif_kernel<<<(NB * 256 + 255) / 256, 256>>>(Y, S1, 256);

    // layer 2: spike inputs -> 8-chain fused compensation
    conv_gemm_v7<128, 64, 8><<<dim3(200, 4), 256>>>(S1, Wg2, bb2, Y, 256, 256, K2TOT, 256);
    lif_kernel<<<(NB * 256 + 255) / 256, 256>>>(Y, S2, 256);

    // layer 3: spike inputs, N=20 (weight rows padded to 32), no BN
    conv_gemm_v7<256, 32, 8><<<dim3(100, 1), 256>>>(S2, Wg3, bb3, Y3, 20, 32, K2TOT, 256);
    lif_out_kernel<<<(NB * 20 + 255) / 256, 256>>>(Y3, (float*)d_out, out_size);
}

// round 8
// speedup vs baseline: 1.2856x; 1.2197x over previous
#include <cuda_runtime.h>
#include <cstdint>

// SNN_Delay: 3x (DCLS gaussian 11-tap temporal conv -> [BN] -> LIF scan), forward only.
// Conv = implicit GEMM, biased FastTwoSum compensated accumulation on packed f32x2.
// R8: ping-pong double-buffered smem (1 sync/tile, global prefetch overlap) on L1/L2;
//     KBLK=2 chains on L1 (dense inputs), KBLK=8 on spike layers.

typedef unsigned long long ull;

#define NT 25
#define NB 1024
#define MROWS (NB*NT)          // 25600
#define K1TOT (11*140)         // 1540
#define K2TOT (11*256)         // 2816

__device__ float g_Wg1[K1TOT*256];
__device__ float g_Wg2[K2TOT*256];
__device__ float g_Wg3[K2TOT*32];
__device__ float g_bb1[256];
__device__ float g_bb2[256];
__device__ float g_bb3[32];
__device__ float g_Y[MROWS*256];
__device__ float g_S1[MROWS*256];
__device__ float g_S2[MROWS*256];
__device__ float g_Y3[MROWS*20];

// ---------------------------------------------------------------------------
__global__ void prep_weights(const float* __restrict__ W, const float* __restrict__ P,
                             const float* __restrict__ SIG, const float* __restrict__ gamma,
                             const float* __restrict__ var, float* __restrict__ Wg,
                             int O, int I, int Ostride)
{
    int idx = blockIdx.x * blockDim.x + threadIdx.x;
    if (idx >= O * I) return;
    int o = idx / I;
    int i = idx - o * I;
    double pc = (double)P[idx] + 5.0;          // MAXD//2 = 5
    double s  = fabs((double)SIG[idx]) + 0.27;
    double g[11];
    double sum = 0.0;
#pragma unroll
    for (int j = 0; j < 11; j++) {
        double d = ((double)j - pc) / s;
        g[j] = exp(-0.5 * d * d);
        sum += g[j];
    }
    double scale = (double)W[idx] / (sum + 1e-7);
    if (gamma) scale *= (double)gamma[o] / sqrt((double)var[o] + 1e-5);
#pragma unroll
    for (int j = 0; j < 11; j++)
        Wg[(size_t)(j * I + i) * Ostride + o] = (float)(g[j] * scale);
}

__global__ void zero_buf(float* p, int n)
{
    int i = blockIdx.x * blockDim.x + threadIdx.x;
    if (i < n) p[i] = 0.f;
}

__global__ void prep_bias(const float* __restrict__ b, const float* __restrict__ gamma,
                          const float* __restrict__ beta, const float* __restrict__ mean,
                          const float* __restrict__ var, float* __restrict__ out, int O)
{
    int o = blockIdx.x * blockDim.x + threadIdx.x;
    if (o >= O) return;
    double v = (double)b[o];
    if (gamma) {
        double sc = (double)gamma[o] / sqrt((double)var[o] + 1e-5);
        v = (v - (double)mean[o]) * sc + (double)beta[o];
    }
    out[o] = (float)v;
}

// ---------------------------------------------------------------------------
// packed f32x2 helpers
// ---------------------------------------------------------------------------
__device__ __forceinline__ ull pack2s(float a) {
    ull r; asm("mov.b64 %0, {%1,%1};" : "=l"(r) : "f"(a)); return r;
}
__device__ __forceinline__ void unpack2(ull v, float& x, float& y) {
    asm("mov.b64 {%0,%1}, %2;" : "=f"(x), "=f"(y) : "l"(v));
}
__device__ __forceinline__ ull pmul(ull a, ull b) {
    ull r; asm("mul.rn.f32x2 %0, %1, %2;" : "=l"(r) : "l"(a), "l"(b)); return r;
}
__device__ __forceinline__ ull padd(ull a, ull b) {
    ull r; asm("add.rn.f32x2 %0, %1, %2;" : "=l"(r) : "l"(a), "l"(b)); return r;
}
__device__ __forceinline__ ull pfma(ull a, ull b, ull c) {
    ull r; asm("fma.rn.f32x2 %0, %1, %2, %3;" : "=l"(r) : "l"(a), "l"(b), "l"(c)); return r;
}

#define NEG1_PK  0xBF800000BF800000ULL   // (-1.f, -1.f)
#define CBIAS    512.0f
#define CBIAS_PK 0x4400000044000000ULL   // (512.f, 512.f)

// ---------------------------------------------------------------------------
// Implicit-GEMM conv, biased FastTwoSum accumulation, packed f32x2.
// Accumulator lanes = two adjacent N columns; A broadcast from duplicated smem.
// C[m,n] = sum_k U[m,k]*Wg[k,n] + bias[n],
//   U[m,k] = X[(m-10)*I + k] if k >= (10 - m%25)*I else 0.
// Wg rows stride Nw (padded); Y rows stride N.
// KBLK: consecutive k products chained via fma before one FastTwoSum.
// PIPE: ping-pong double-buffered smem with global prefetch (1 sync/tile).
// ---------------------------------------------------------------------------
template<int BM, int BN, int KBLK, bool PIPE>
__global__ void __launch_bounds__(256)
conv_gemm_v8(const float* __restrict__ X, const float* __restrict__ Wg,
             const float* __restrict__ bias, float* __restrict__ Y,
             int N, int Nw, int Ktot, int I)
{
    constexpr int NBUF  = PIPE ? 2 : 1;
    constexpr int APASS = BM / 64;       // row passes for A loads
    constexpr int CG    = BN / 4;        // col groups
    static_assert(256 / CG * 8 == BM, "compute map covers BM");
    static_assert(16 % KBLK == 0, "KBLK divides 16");
    __shared__ ull   As2[NBUF][BM][18];  // dup (a,a); [row][kk]
    __shared__ float Bs[NBUF][16][BN + 4];

    const int tid = threadIdx.x;
    const int bm = blockIdx.x * BM;
    const int bn = blockIdx.y * BN;

    // A-load geometry
    const int arow = tid >> 2;          // 0..63
    const int akq  = (tid & 3) * 4;     // 0,4,8,12
    long abase[APASS];
    int  alow[APASS];
#pragma unroll
    for (int r = 0; r < APASS; r++) {
        int m = bm + arow + r * 64;
        int t = m % 25;
        abase[r] = (long)(m - 10) * I;
        alow[r]  = (t < 10) ? (10 - t) * I : 0;   // multiple of 4 (I%4==0)
    }
    // B-load geometry
    const int bkrow = tid / CG;          // k-row
    const int bcq   = (tid % CG) * 4;    // col offset

    ull acc[8][2], cmp[8][2];            // [row q][col pair]
#pragma unroll
    for (int q = 0; q < 8; q++) {
        acc[q][0] = CBIAS_PK; acc[q][1] = CBIAS_PK;
        cmp[q][0] = 0ull;     cmp[q][1] = 0ull;
    }

    const int ty = tid / CG;            // 8-row group
    const int tx = tid % CG;            // 4-col group

    const int ntiles = (Ktot + 15) / 16;

    float4 va[APASS];
    float4 vb = make_float4(0.f, 0.f, 0.f, 0.f);

    auto load_tile = [&](int ti) {
        int k0 = ti * 16;
#pragma unroll
        for (int r = 0; r < APASS; r++) {
            int k = k0 + akq;
            va[r] = make_float4(0.f, 0.f, 0.f, 0.f);
            if (k >= alow[r] && k < Ktot)       // Ktot%4==0 -> vector-exact
                va[r] = *reinterpret_cast<const float4*>(X + abase[r] + k);
        }
        if (bkrow < 16) {
            int k = k0 + bkrow;
            vb = make_float4(0.f, 0.f, 0.f, 0.f);
            if (k < Ktot)
                vb = *reinterpret_cast<const float4*>(Wg + (size_t)k * Nw + bn + bcq);
        }
    };
    auto store_tile = [&](int buf) {
#pragma unroll
        for (int r = 0; r < APASS; r++) {
            int row = arow + r * 64;
            ulonglong2 w0; w0.x = pack2s(va[r].x); w0.y = pack2s(va[r].y);
            ulonglong2 w1; w1.x = pack2s(va[r].z); w1.y = pack2s(va[r].w);
            *reinterpret_cast<ulonglong2*>(&As2[buf][row][akq])     = w0;
            *reinterpret_cast<ulonglong2*>(&As2[buf][row][akq + 2]) = w1;
        }
        if (bkrow < 16)
            *reinterpret_cast<float4*>(&Bs[buf][bkrow][bcq]) = vb;
    };
    auto compute = [&](int buf) {
#pragma unroll
        for (int kb = 0; kb < 16; kb += KBLK) {
            ull bq0[KBLK], bq1[KBLK];
#pragma unroll
            for (int kk = 0; kk < KBLK; kk++) {
                ulonglong2 bb = *reinterpret_cast<const ulonglong2*>(
                    &Bs[buf][kb + kk][tx * 4]);
                bq0[kk] = bb.x; bq1[kk] = bb.y;
            }
#pragma unroll
            for (int q = 0; q < 8; q++) {
                ull a[KBLK];
                if (KBLK == 1) {
                    a[0] = As2[buf][ty * 8 + q][kb];
                } else {
#pragma unroll
                    for (int kk = 0; kk < KBLK; kk += 2) {
                        ulonglong2 av = *reinterpret_cast<const ulonglong2*>(
                            &As2[buf][ty * 8 + q][kb + kk]);
                        a[kk] = av.x; a[kk + 1] = av.y;
                    }
                }
#pragma unroll
                for (int cp = 0; cp < 2; cp++) {
                    ull pr = pmul(a[0], cp ? bq1[0] : bq0[0]);
#pragma unroll
                    for (int kk = 1; kk < KBLK; kk++)
                        pr = pfma(a[kk], cp ? bq1[kk] : bq0[kk], pr);
                    ull s = acc[q][cp];
                    ull t = padd(s, pr);
                    ull d = pfma(s, (ull)NEG1_PK, t);   // t - s  (exact)
                    ull e = pfma(d, (ull)NEG1_PK, pr);  // pr - d (exact)
                    acc[q][cp] = t;
                    cmp[q][cp] = padd(cmp[q][cp], e);
                }
            }
        }
    };

    if (PIPE) {
        load_tile(0);
        store_tile(0);
        __syncthreads();
        for (int ti = 0; ti < ntiles; ti++) {
            bool more = (ti + 1 < ntiles);
            if (more) load_tile(ti + 1);        // overlap global latency with compute
            compute(ti & 1);
            if (more) {
                store_tile((ti + 1) & 1);
                __syncthreads();
            }
        }
    } else {
        for (int ti = 0; ti < ntiles; ti++) {
            if (ti > 0) __syncthreads();        // protect buffer from prior compute
            load_tile(ti);
            store_tile(0);
            __syncthreads();
            compute(0);
        }
    }

#pragma unroll
    for (int q = 0; q < 8; q++) {
        int m = bm + ty * 8 + q;
#pragma unroll
        for (int cp = 0; cp < 2; cp++) {
            int n = bn + tx * 4 + cp * 2;
            float t0, t1, c0, c1;
            unpack2(acc[q][cp], t0, t1);
            unpack2(cmp[q][cp], c0, c1);
            if (n < N) {
                float v = __fadd_rn(__fsub_rn(t0, CBIAS), c0);
                Y[(size_t)m * N + n] = __fadd_rn(v, bias[n]);
            }
            if (n + 1 < N) {
                float v = __fadd_rn(__fsub_rn(t1, CBIAS), c1);
                Y[(size_t)m * N + n + 1] = __fadd_rn(v, bias[n + 1]);
            }
        }
    }
}

// ---------------------------------------------------------------------------
// LIF scan in fp64 (snntorch Leaky, reset='subtract'). Layout (B,T,C).
// ---------------------------------------------------------------------------
__global__ void lif_kernel(const float* __restrict__ Y, float* __restrict__ S, int C)
{
    int idx = blockIdx.x * blockDim.x + threadIdx.x;
    if (idx >= NB * C) return;
    int b = idx / C;
    int c = idx - b * C;
    const float* y = Y + (size_t)b * NT * C + c;
    float* s = S + (size_t)b * NT * C + c;
    double mem = 0.0;
#pragma unroll
    for (int t = 0; t < NT; t++) {
        double reset = (mem > 1.0) ? 1.0 : 0.0;
        mem = 0.95 * mem + (double)y[t * C] - reset;
        s[t * C] = (mem > 1.0) ? 1.0f : 0.0f;
    }
}

// Final LIF: layer-3 Y row stride 20. Emits spk3 (T,B,20) then mem3 (T,B,20).
__global__ void lif_out_kernel(const float* __restrict__ Y, float* __restrict__ out,
                               int out_size)
{
    int idx = blockIdx.x * blockDim.x + threadIdx.x;
    if (idx >= NB * 20) return;
    int b = idx / 20;
    int c = idx - b * 20;
    bool have_mem = (out_size >= 2 * NT * NB * 20);
    double mem = 0.0;
#pragma unroll
    for (int t = 0; t < NT; t++) {
        double reset = (mem > 1.0) ? 1.0 : 0.0;
        mem = 0.95 * mem + (double)Y[((size_t)b * NT + t) * 20 + c] - reset;
        float spk = (mem > 1.0) ? 1.0f : 0.0f;
        out[(size_t)t * NB * 20 + b * 20 + c] = spk;
        if (have_mem)
            out[(size_t)NT * NB * 20 + (size_t)t * NB * 20 + b * 20 + c] = (float)mem;
    }
}

// ---------------------------------------------------------------------------
extern "C" void kernel_launch(void* const* d_in, const int* in_sizes, int n_in,
                              void* d_out, int out_size)
{
    const float* data = (const float*)d_in[0];
    const float* W1   = (const float*)d_in[1];
    const float* b1   = (const float*)d_in[2];
    const float* P1   = (const float*)d_in[3];
    const float* SIG1 = (const float*)d_in[4];
    const float* g1   = (const float*)d_in[5];
    const float* be1  = (const float*)d_in[6];
    const float* mu1  = (const float*)d_in[7];
    const float* va1  = (const float*)d_in[8];
    const float* W2   = (const float*)d_in[9];
    const float* b2   = (const float*)d_in[10];
    const float* P2   = (const float*)d_in[11];
    const float* SIG2 = (const float*)d_in[12];
    const float* g2   = (const float*)d_in[13];
    const float* be2  = (const float*)d_in[14];
    const float* mu2  = (const float*)d_in[15];
    const float* va2  = (const float*)d_in[16];
    const float* W3   = (const float*)d_in[17];
    const float* b3   = (const float*)d_in[18];
    const float* P3   = (const float*)d_in[19];
    const float* SIG3 = (const float*)d_in[20];

    float *Wg1, *Wg2, *Wg3, *bb1, *bb2, *bb3, *Y, *S1, *S2, *Y3;
    cudaGetSymbolAddress((void**)&Wg1, g_Wg1);
    cudaGetSymbolAddress((void**)&Wg2, g_Wg2);
    cudaGetSymbolAddress((void**)&Wg3, g_Wg3);
    cudaGetSymbolAddress((void**)&bb1, g_bb1);
    cudaGetSymbolAddress((void**)&bb2, g_bb2);
    cudaGetSymbolAddress((void**)&bb3, g_bb3);
    cudaGetSymbolAddress((void**)&Y,   g_Y);
    cudaGetSymbolAddress((void**)&S1,  g_S1);
    cudaGetSymbolAddress((void**)&S2,  g_S2);
    cudaGetSymbolAddress((void**)&Y3,  g_Y3);

    // weight/bias prep (tiny). Layer-3 weights padded to 32 cols (zeros).
    zero_buf<<<(K2TOT * 32 + 255) / 256, 256>>>(Wg3, K2TOT * 32);
    prep_weights<<<(256 * 140 + 255) / 256, 256>>>(W1, P1, SIG1, g1, va1, Wg1, 256, 140, 256);
    prep_weights<<<(256 * 256 + 255) / 256, 256>>>(W2, P2, SIG2, g2, va2, Wg2, 256, 256, 256);
    prep_weights<<<(20 * 256 + 255) / 256, 256>>>(W3, P3, SIG3, nullptr, nullptr, Wg3, 20, 256, 32);
    prep_bias<<<1, 256>>>(b1, g1, be1, mu1, va1, bb1, 256);
    prep_bias<<<1, 256>>>(b2, g2, be2, mu2, va2, bb2, 256);
    prep_bias<<<1, 32>>>(b3, nullptr, nullptr, nullptr, nullptr, bb3, 20);

    // layer 1: dense inputs -> KBLK=2 chains, double-buffered
    conv_gemm_v8<128, 64, 2, true><<<dim3(200, 4), 256>>>(data, Wg1, bb1, Y, 256, 256, K1TOT, 140);
    lif_kernel<<<(NB * 256 + 255) / 256, 256>>>(Y, S1, 256);

    // layer 2: spike inputs -> KBLK=8 chains, double-buffered
    conv_gemm_v8<128, 64, 8, true><<<dim3(200, 4), 256>>>(S1, Wg2, bb2, Y, 256, 256, K2TOT, 256);
    lif_kernel<<<(NB * 256 + 255) / 256, 256>>>(Y, S2, 256);

    // layer 3: spike inputs, N=20 (weight rows padded to 32), single-buffered
    conv_gemm_v8<256, 32, 8, false><<<dim3(100, 1), 256>>>(S2, Wg3, bb3, Y3, 20, 32, K2TOT, 256);
    lif_out_kernel<<<(NB * 20 + 255) / 256, 256>>>(Y3, (float*)d_out, out_size);
}

// round 9
// speedup vs baseline: 1.3192x; 1.0262x over previous
#include <cuda_runtime.h>
#include <cstdint>

// SNN_Delay: 3x (DCLS gaussian 11-tap temporal conv -> [BN] -> LIF scan), forward only.
// Conv = implicit GEMM, biased FastTwoSum compensated accumulation on packed f32x2.
// R9: L1 KBLK 2->4 (dense-input chain of 4 products per compensation step).

typedef unsigned long long ull;

#define NT 25
#define NB 1024
#define MROWS (NB*NT)          // 25600
#define K1TOT (11*140)         // 1540
#define K2TOT (11*256)         // 2816

__device__ float g_Wg1[K1TOT*256];
__device__ float g_Wg2[K2TOT*256];
__device__ float g_Wg3[K2TOT*32];
__device__ float g_bb1[256];
__device__ float g_bb2[256];
__device__ float g_bb3[32];
__device__ float g_Y[MROWS*256];
__device__ float g_S1[MROWS*256];
__device__ float g_S2[MROWS*256];
__device__ float g_Y3[MROWS*20];

// ---------------------------------------------------------------------------
__global__ void prep_weights(const float* __restrict__ W, const float* __restrict__ P,
                             const float* __restrict__ SIG, const float* __restrict__ gamma,
                             const float* __restrict__ var, float* __restrict__ Wg,
                             int O, int I, int Ostride)
{
    int idx = blockIdx.x * blockDim.x + threadIdx.x;
    if (idx >= O * I) return;
    int o = idx / I;
    int i = idx - o * I;
    double pc = (double)P[idx] + 5.0;          // MAXD//2 = 5
    double s  = fabs((double)SIG[idx]) + 0.27;
    double g[11];
    double sum = 0.0;
#pragma unroll
    for (int j = 0; j < 11; j++) {
        double d = ((double)j - pc) / s;
        g[j] = exp(-0.5 * d * d);
        sum += g[j];
    }
    double scale = (double)W[idx] / (sum + 1e-7);
    if (gamma) scale *= (double)gamma[o] / sqrt((double)var[o] + 1e-5);
#pragma unroll
    for (int j = 0; j < 11; j++)
        Wg[(size_t)(j * I + i) * Ostride + o] = (float)(g[j] * scale);
}

__global__ void zero_buf(float* p, int n)
{
    int i = blockIdx.x * blockDim.x + threadIdx.x;
    if (i < n) p[i] = 0.f;
}

__global__ void prep_bias(const float* __restrict__ b, const float* __restrict__ gamma,
                          const float* __restrict__ beta, const float* __restrict__ mean,
                          const float* __restrict__ var, float* __restrict__ out, int O)
{
    int o = blockIdx.x * blockDim.x + threadIdx.x;
    if (o >= O) return;
    double v = (double)b[o];
    if (gamma) {
        double sc = (double)gamma[o] / sqrt((double)var[o] + 1e-5);
        v = (v - (double)mean[o]) * sc + (double)beta[o];
    }
    out[o] = (float)v;
}

// ---------------------------------------------------------------------------
// packed f32x2 helpers
// ---------------------------------------------------------------------------
__device__ __forceinline__ ull pack2s(float a) {
    ull r; asm("mov.b64 %0, {%1,%1};" : "=l"(r) : "f"(a)); return r;
}
__device__ __forceinline__ void unpack2(ull v, float& x, float& y) {
    asm("mov.b64 {%0,%1}, %2;" : "=f"(x), "=f"(y) : "l"(v));
}
__device__ __forceinline__ ull pmul(ull a, ull b) {
    ull r; asm("mul.rn.f32x2 %0, %1, %2;" : "=l"(r) : "l"(a), "l"(b)); return r;
}
__device__ __forceinline__ ull padd(ull a, ull b) {
    ull r; asm("add.rn.f32x2 %0, %1, %2;" : "=l"(r) : "l"(a), "l"(b)); return r;
}
__device__ __forceinline__ ull pfma(ull a, ull b, ull c) {
    ull r; asm("fma.rn.f32x2 %0, %1, %2, %3;" : "=l"(r) : "l"(a), "l"(b), "l"(c)); return r;
}

#define NEG1_PK  0xBF800000BF800000ULL   // (-1.f, -1.f)
#define CBIAS    512.0f
#define CBIAS_PK 0x4400000044000000ULL   // (512.f, 512.f)

// ---------------------------------------------------------------------------
// Implicit-GEMM conv, biased FastTwoSum accumulation, packed f32x2.
// Accumulator lanes = two adjacent N columns; A broadcast from duplicated smem.
// C[m,n] = sum_k U[m,k]*Wg[k,n] + bias[n],
//   U[m,k] = X[(m-10)*I + k] if k >= (10 - m%25)*I else 0.
// Wg rows stride Nw (padded); Y rows stride N.
// KBLK: consecutive k products chained via fma before one FastTwoSum.
// PIPE: ping-pong double-buffered smem with global prefetch (1 sync/tile).
// ---------------------------------------------------------------------------
template<int BM, int BN, int KBLK, bool PIPE>
__global__ void __launch_bounds__(256)
conv_gemm_v9(const float* __restrict__ X, const float* __restrict__ Wg,
             const float* __restrict__ bias, float* __restrict__ Y,
             int N, int Nw, int Ktot, int I)
{
    constexpr int NBUF  = PIPE ? 2 : 1;
    constexpr int APASS = BM / 64;       // row passes for A loads
    constexpr int CG    = BN / 4;        // col groups
    static_assert(256 / CG * 8 == BM, "compute map covers BM");
    static_assert(16 % KBLK == 0, "KBLK divides 16");
    __shared__ ull   As2[NBUF][BM][18];  // dup (a,a); [row][kk]
    __shared__ float Bs[NBUF][16][BN + 4];

    const int tid = threadIdx.x;
    const int bm = blockIdx.x * BM;
    const int bn = blockIdx.y * BN;

    // A-load geometry
    const int arow = tid >> 2;          // 0..63
    const int akq  = (tid & 3) * 4;     // 0,4,8,12
    long abase[APASS];
    int  alow[APASS];
#pragma unroll
    for (int r = 0; r < APASS; r++) {
        int m = bm + arow + r * 64;
        int t = m % 25;
        abase[r] = (long)(m - 10) * I;
        alow[r]  = (t < 10) ? (10 - t) * I : 0;   // multiple of 4 (I%4==0)
    }
    // B-load geometry
    const int bkrow = tid / CG;          // k-row
    const int bcq   = (tid % CG) * 4;    // col offset

    ull acc[8][2], cmp[8][2];            // [row q][col pair]
#pragma unroll
    for (int q = 0; q < 8; q++) {
        acc[q][0] = CBIAS_PK; acc[q][1] = CBIAS_PK;
        cmp[q][0] = 0ull;     cmp[q][1] = 0ull;
    }

    const int ty = tid / CG;            // 8-row group
    const int tx = tid % CG;            // 4-col group

    const int ntiles = (Ktot + 15) / 16;

    float4 va[APASS];
    float4 vb = make_float4(0.f, 0.f, 0.f, 0.f);

    auto load_tile = [&](int ti) {
        int k0 = ti * 16;
#pragma unroll
        for (int r = 0; r < APASS; r++) {
            int k = k0 + akq;
            va[r] = make_float4(0.f, 0.f, 0.f, 0.f);
            if (k >= alow[r] && k < Ktot)       // Ktot%4==0 -> vector-exact
                va[r] = *reinterpret_cast<const float4*>(X + abase[r] + k);
        }
        if (bkrow < 16) {
            int k = k0 + bkrow;
            vb = make_float4(0.f, 0.f, 0.f, 0.f);
            if (k < Ktot)
                vb = *reinterpret_cast<const float4*>(Wg + (size_t)k * Nw + bn + bcq);
        }
    };
    auto store_tile = [&](int buf) {
#pragma unroll
        for (int r = 0; r < APASS; r++) {
            int row = arow + r * 64;
            ulonglong2 w0; w0.x = pack2s(va[r].x); w0.y = pack2s(va[r].y);
            ulonglong2 w1; w1.x = pack2s(va[r].z); w1.y = pack2s(va[r].w);
            *reinterpret_cast<ulonglong2*>(&As2[buf][row][akq])     = w0;
            *reinterpret_cast<ulonglong2*>(&As2[buf][row][akq + 2]) = w1;
        }
        if (bkrow < 16)
            *reinterpret_cast<float4*>(&Bs[buf][bkrow][bcq]) = vb;
    };
    auto compute = [&](int buf) {
#pragma unroll
        for (int kb = 0; kb < 16; kb += KBLK) {
            ull bq0[KBLK], bq1[KBLK];
#pragma unroll
            for (int kk = 0; kk < KBLK; kk++) {
                ulonglong2 bb = *reinterpret_cast<const ulonglong2*>(
                    &Bs[buf][kb + kk][tx * 4]);
                bq0[kk] = bb.x; bq1[kk] = bb.y;
            }
#pragma unroll
            for (int q = 0; q < 8; q++) {
                ull a[KBLK];
                if (KBLK == 1) {
                    a[0] = As2[buf][ty * 8 + q][kb];
                } else {
#pragma unroll
                    for (int kk = 0; kk < KBLK; kk += 2) {
                        ulonglong2 av = *reinterpret_cast<const ulonglong2*>(
                            &As2[buf][ty * 8 + q][kb + kk]);
                        a[kk] = av.x; a[kk + 1] = av.y;
                    }
                }
#pragma unroll
                for (int cp = 0; cp < 2; cp++) {
                    ull pr = pmul(a[0], cp ? bq1[0] : bq0[0]);
#pragma unroll
                    for (int kk = 1; kk < KBLK; kk++)
                        pr = pfma(a[kk], cp ? bq1[kk] : bq0[kk], pr);
                    ull s = acc[q][cp];
                    ull t = padd(s, pr);
                    ull d = pfma(s, (ull)NEG1_PK, t);   // t - s  (exact)
                    ull e = pfma(d, (ull)NEG1_PK, pr);  // pr - d (exact)
                    acc[q][cp] = t;
                    cmp[q][cp] = padd(cmp[q][cp], e);
                }
            }
        }
    };

    if (PIPE) {
        load_tile(0);
        store_tile(0);
        __syncthreads();
        for (int ti = 0; ti < ntiles; ti++) {
            bool more = (ti + 1 < ntiles);
            if (more) load_tile(ti + 1);        // overlap global latency with compute
            compute(ti & 1);
            if (more) {
                store_tile((ti + 1) & 1);
                __syncthreads();
            }
        }
    } else {
        for (int ti = 0; ti < ntiles; ti++) {
            if (ti > 0) __syncthreads();        // protect buffer from prior compute
            load_tile(ti);
            store_tile(0);
            __syncthreads();
            compute(0);
        }
    }

#pragma unroll
    for (int q = 0; q < 8; q++) {
        int m = bm + ty * 8 + q;
#pragma unroll
        for (int cp = 0; cp < 2; cp++) {
            int n = bn + tx * 4 + cp * 2;
            float t0, t1, c0, c1;
            unpack2(acc[q][cp], t0, t1);
            unpack2(cmp[q][cp], c0, c1);
            if (n < N) {
                float v = __fadd_rn(__fsub_rn(t0, CBIAS), c0);
                Y[(size_t)m * N + n] = __fadd_rn(v, bias[n]);
            }
            if (n + 1 < N) {
                float v = __fadd_rn(__fsub_rn(t1, CBIAS), c1);
                Y[(size_t)m * N + n + 1] = __fadd_rn(v, bias[n + 1]);
            }
        }
    }
}

// ---------------------------------------------------------------------------
// LIF scan in fp64 (snntorch Leaky, reset='subtract'). Layout (B,T,C).
// ---------------------------------------------------------------------------
__global__ void lif_kernel(const float* __restrict__ Y, float* __restrict__ S, int C)
{
    int idx = blockIdx.x * blockDim.x + threadIdx.x;
    if (idx >= NB * C) return;
    int b = idx / C;
    int c = idx - b * C;
    const float* y = Y + (size_t)b * NT * C + c;
    float* s = S + (size_t)b * NT * C + c;
    double mem = 0.0;
#pragma unroll
    for (int t = 0; t < NT; t++) {
        double reset = (mem > 1.0) ? 1.0 : 0.0;
        mem = 0.95 * mem + (double)y[t * C] - reset;
        s[t * C] = (mem > 1.0) ? 1.0f : 0.0f;
    }
}

// Final LIF: layer-3 Y row stride 20. Emits spk3 (T,B,20) then mem3 (T,B,20).
__global__ void lif_out_kernel(const float* __restrict__ Y, float* __restrict__ out,
                               int out_size)
{
    int idx = blockIdx.x * blockDim.x + threadIdx.x;
    if (idx >= NB * 20) return;
    int b = idx / 20;
    int c = idx - b * 20;
    bool have_mem = (out_size >= 2 * NT * NB * 20);
    double mem = 0.0;
#pragma unroll
    for (int t = 0; t < NT; t++) {
        double reset = (mem > 1.0) ? 1.0 : 0.0;
        mem = 0.95 * mem + (double)Y[((size_t)b * NT + t) * 20 + c] - reset;
        float spk = (mem > 1.0) ? 1.0f : 0.0f;
        out[(size_t)t * NB * 20 + b * 20 + c] = spk;
        if (have_mem)
            out[(size_t)NT * NB * 20 + (size_t)t * NB * 20 + b * 20 + c] = (float)mem;
    }
}

// ---------------------------------------------------------------------------
extern "C" void kernel_launch(void* const* d_in, const int* in_sizes, int n_in,
                              void* d_out, int out_size)
{
    const float* data = (const float*)d_in[0];
    const float* W1   = (const float*)d_in[1];
    const float* b1   = (const float*)d_in[2];
    const float* P1   = (const float*)d_in[3];
    const float* SIG1 = (const float*)d_in[4];
    const float* g1   = (const float*)d_in[5];
    const float* be1  = (const float*)d_in[6];
    const float* mu1  = (const float*)d_in[7];
    const float* va1  = (const float*)d_in[8];
    const float* W2   = (const float*)d_in[9];
    const float* b2   = (const float*)d_in[10];
    const float* P2   = (const float*)d_in[11];
    const float* SIG2 = (const float*)d_in[12];
    const float* g2   = (const float*)d_in[13];
    const float* be2  = (const float*)d_in[14];
    const float* mu2  = (const float*)d_in[15];
    const float* va2  = (const float*)d_in[16];
    const float* W3   = (const float*)d_in[17];
    const float* b3   = (const float*)d_in[18];
    const float* P3   = (const float*)d_in[19];
    const float* SIG3 = (const float*)d_in[20];

    float *Wg1, *Wg2, *Wg3, *bb1, *bb2, *bb3, *Y, *S1, *S2, *Y3;
    cudaGetSymbolAddress((void**)&Wg1, g_Wg1);
    cudaGetSymbolAddress((void**)&Wg2, g_Wg2);
    cudaGetSymbolAddress((void**)&Wg3, g_Wg3);
    cudaGetSymbolAddress((void**)&bb1, g_bb1);
    cudaGetSymbolAddress((void**)&bb2, g_bb2);
    cudaGetSymbolAddress((void**)&bb3, g_bb3);
    cudaGetSymbolAddress((void**)&Y,   g_Y);
    cudaGetSymbolAddress((void**)&S1,  g_S1);
    cudaGetSymbolAddress((void**)&S2,  g_S2);
    cudaGetSymbolAddress((void**)&Y3,  g_Y3);

    // weight/bias prep (tiny). Layer-3 weights padded to 32 cols (zeros).
    zero_buf<<<(K2TOT * 32 + 255) / 256, 256>>>(Wg3, K2TOT * 32);
    prep_weights<<<(256 * 140 + 255) / 256, 256>>>(W1, P1, SIG1, g1, va1, Wg1, 256, 140, 256);
    prep_weights<<<(256 * 256 + 255) / 256, 256>>>(W2, P2, SIG2, g2, va2, Wg2, 256, 256, 256);
    prep_weights<<<(20 * 256 + 255) / 256, 256>>>(W3, P3, SIG3, nullptr, nullptr, Wg3, 20, 256, 32);
    prep_bias<<<1, 256>>>(b1, g1, be1, mu1, va1, bb1, 256);
    prep_bias<<<1, 256>>>(b2, g2, be2, mu2, va2, bb2, 256);
    prep_bias<<<1, 32>>>(b3, nullptr, nullptr, nullptr, nullptr, bb3, 20);

    // layer 1: dense inputs -> KBLK=4 chains, double-buffered
    conv_gemm_v9<128, 64, 4, true><<<dim3(200, 4), 256>>>(data, Wg1, bb1, Y, 256, 256, K1TOT, 140);
    lif_kernel<<<(NB * 256 + 255) / 256, 256>>>(Y, S1, 256);

    // layer 2: spike inputs -> KBLK=8 chains, double-buffered
    conv_gemm_v9<128, 64, 8, true><<<dim3(200, 4), 256>>>(S1, Wg2, bb2, Y, 256, 256, K2TOT, 256);
    lif_kernel<<<(NB * 256 + 255) / 256, 256>>>(Y, S2, 256);

    // layer 3: spike inputs, N=20 (weight rows padded to 32), single-buffered
    conv_gemm_v9<256, 32, 8, false><<<dim3(100, 1), 256>>>(S2, Wg3, bb3, Y3, 20, 32, K2TOT, 256);
    lif_out_kernel<<<(NB * 20 + 255) / 256, 256>>>(Y3, (float*)d_out, out_size);
}

// round 11
// speedup vs baseline: 1.3782x; 1.0447x over previous
#include <cuda_runtime.h>
#include <cstdint>

// SNN_Delay: 3x (DCLS gaussian 11-tap temporal conv -> [BN] -> LIF scan), forward only.
// Conv = implicit GEMM, biased FastTwoSum compensated accumulation on packed f32x2.
// R11: revert tensor experiment (tcgen05 not compilable via harness's compute_103 PTX);
//      scalar path with KBLK=8 chains on ALL layers (L1 bumped 4->8).

typedef unsigned long long ull;

#define NT 25
#define NB 1024
#define MROWS (NB*NT)          // 25600
#define K1TOT (11*140)         // 1540
#define K2TOT (11*256)         // 2816

__device__ float g_Wg1[K1TOT*256];
__device__ float g_Wg2[K2TOT*256];
__device__ float g_Wg3[K2TOT*32];
__device__ float g_bb1[256];
__device__ float g_bb2[256];
__device__ float g_bb3[32];
__device__ float g_Y[MROWS*256];
__device__ float g_S1[MROWS*256];
__device__ float g_S2[MROWS*256];
__device__ float g_Y3[MROWS*20];

// ---------------------------------------------------------------------------
__global__ void prep_weights(const float* __restrict__ W, const float* __restrict__ P,
                             const float* __restrict__ SIG, const float* __restrict__ gamma,
                             const float* __restrict__ var, float* __restrict__ Wg,
                             int O, int I, int Ostride)
{
    int idx = blockIdx.x * blockDim.x + threadIdx.x;
    if (idx >= O * I) return;
    int o = idx / I;
    int i = idx - o * I;
    double pc = (double)P[idx] + 5.0;          // MAXD//2 = 5
    double s  = fabs((double)SIG[idx]) + 0.27;
    double g[11];
    double sum = 0.0;
#pragma unroll
    for (int j = 0; j < 11; j++) {
        double d = ((double)j - pc) / s;
        g[j] = exp(-0.5 * d * d);
        sum += g[j];
    }
    double scale = (double)W[idx] / (sum + 1e-7);
    if (gamma) scale *= (double)gamma[o] / sqrt((double)var[o] + 1e-5);
#pragma unroll
    for (int j = 0; j < 11; j++)
        Wg[(size_t)(j * I + i) * Ostride + o] = (float)(g[j] * scale);
}

__global__ void zero_buf(float* p, int n)
{
    int i = blockIdx.x * blockDim.x + threadIdx.x;
    if (i < n) p[i] = 0.f;
}

__global__ void prep_bias(const float* __restrict__ b, const float* __restrict__ gamma,
                          const float* __restrict__ beta, const float* __restrict__ mean,
                          const float* __restrict__ var, float* __restrict__ out, int O)
{
    int o = blockIdx.x * blockDim.x + threadIdx.x;
    if (o >= O) return;
    double v = (double)b[o];
    if (gamma) {
        double sc = (double)gamma[o] / sqrt((double)var[o] + 1e-5);
        v = (v - (double)mean[o]) * sc + (double)beta[o];
    }
    out[o] = (float)v;
}

// ---------------------------------------------------------------------------
// packed f32x2 helpers
// ---------------------------------------------------------------------------
__device__ __forceinline__ ull pack2s(float a) {
    ull r; asm("mov.b64 %0, {%1,%1};" : "=l"(r) : "f"(a)); return r;
}
__device__ __forceinline__ void unpack2(ull v, float& x, float& y) {
    asm("mov.b64 {%0,%1}, %2;" : "=f"(x), "=f"(y) : "l"(v));
}
__device__ __forceinline__ ull pmul(ull a, ull b) {
    ull r; asm("mul.rn.f32x2 %0, %1, %2;" : "=l"(r) : "l"(a), "l"(b)); return r;
}
__device__ __forceinline__ ull padd(ull a, ull b) {
    ull r; asm("add.rn.f32x2 %0, %1, %2;" : "=l"(r) : "l"(a), "l"(b)); return r;
}
__device__ __forceinline__ ull pfma(ull a, ull b, ull c) {
    ull r; asm("fma.rn.f32x2 %0, %1, %2, %3;" : "=l"(r) : "l"(a), "l"(b), "l"(c)); return r;
}

#define NEG1_PK  0xBF800000BF800000ULL   // (-1.f, -1.f)
#define CBIAS    512.0f
#define CBIAS_PK 0x4400000044000000ULL   // (512.f, 512.f)

// ---------------------------------------------------------------------------
// Implicit-GEMM conv, biased FastTwoSum accumulation, packed f32x2.
// Accumulator lanes = two adjacent N columns; A broadcast from duplicated smem.
// C[m,n] = sum_k U[m,k]*Wg[k,n] + bias[n],
//   U[m,k] = X[(m-10)*I + k] if k >= (10 - m%25)*I else 0.
// Wg rows stride Nw (padded); Y rows stride N.
// KBLK: consecutive k products chained via fma before one FastTwoSum.
// PIPE: ping-pong double-buffered smem with global prefetch (1 sync/tile).
// ---------------------------------------------------------------------------
template<int BM, int BN, int KBLK, bool PIPE>
__global__ void __launch_bounds__(256)
conv_gemm_v11(const float* __restrict__ X, const float* __restrict__ Wg,
              const float* __restrict__ bias, float* __restrict__ Y,
              int N, int Nw, int Ktot, int I)
{
    constexpr int NBUF  = PIPE ? 2 : 1;
    constexpr int APASS = BM / 64;       // row passes for A loads
    constexpr int CG    = BN / 4;        // col groups
    static_assert(256 / CG * 8 == BM, "compute map covers BM");
    static_assert(16 % KBLK == 0, "KBLK divides 16");
    __shared__ ull   As2[NBUF][BM][18];  // dup (a,a); [row][kk]
    __shared__ float Bs[NBUF][16][BN + 4];

    const int tid = threadIdx.x;
    const int bm = blockIdx.x * BM;
    const int bn = blockIdx.y * BN;

    // A-load geometry
    const int arow = tid >> 2;          // 0..63
    const int akq  = (tid & 3) * 4;     // 0,4,8,12
    long abase[APASS];
    int  alow[APASS];
#pragma unroll
    for (int r = 0; r < APASS; r++) {
        int m = bm + arow + r * 64;
        int t = m % 25;
        abase[r] = (long)(m - 10) * I;
        alow[r]  = (t < 10) ? (10 - t) * I : 0;   // multiple of 4 (I%4==0)
    }
    // B-load geometry
    const int bkrow = tid / CG;          // k-row
    const int bcq   = (tid % CG) * 4;    // col offset

    ull acc[8][2], cmp[8][2];            // [row q][col pair]
#pragma unroll
    for (int q = 0; q < 8; q++) {
        acc[q][0] = CBIAS_PK; acc[q][1] = CBIAS_PK;
        cmp[q][0] = 0ull;     cmp[q][1] = 0ull;
    }

    const int ty = tid / CG;            // 8-row group
    const int tx = tid % CG;            // 4-col group

    const int ntiles = (Ktot + 15) / 16;

    float4 va[APASS];
    float4 vb = make_float4(0.f, 0.f, 0.f, 0.f);

    auto load_tile = [&](int ti) {
        int k0 = ti * 16;
#pragma unroll
        for (int r = 0; r < APASS; r++) {
            int k = k0 + akq;
            va[r] = make_float4(0.f, 0.f, 0.f, 0.f);
            if (k >= alow[r] && k < Ktot)       // Ktot%4==0 -> vector-exact
                va[r] = *reinterpret_cast<const float4*>(X + abase[r] + k);
        }
        if (bkrow < 16) {
            int k = k0 + bkrow;
            vb = make_float4(0.f, 0.f, 0.f, 0.f);
            if (k < Ktot)
                vb = *reinterpret_cast<const float4*>(Wg + (size_t)k * Nw + bn + bcq);
        }
    };
    auto store_tile = [&](int buf) {
#pragma unroll
        for (int r = 0; r < APASS; r++) {
            int row = arow + r * 64;
            ulonglong2 w0; w0.x = pack2s(va[r].x); w0.y = pack2s(va[r].y);
            ulonglong2 w1; w1.x = pack2s(va[r].z); w1.y = pack2s(va[r].w);
            *reinterpret_cast<ulonglong2*>(&As2[buf][row][akq])     = w0;
            *reinterpret_cast<ulonglong2*>(&As2[buf][row][akq + 2]) = w1;
        }
        if (bkrow < 16)
            *reinterpret_cast<float4*>(&Bs[buf][bkrow][bcq]) = vb;
    };
    auto compute = [&](int buf) {
#pragma unroll
        for (int kb = 0; kb < 16; kb += KBLK) {
            ull bq0[KBLK], bq1[KBLK];
#pragma unroll
            for (int kk = 0; kk < KBLK; kk++) {
                ulonglong2 bb = *reinterpret_cast<const ulonglong2*>(
                    &Bs[buf][kb + kk][tx * 4]);
                bq0[kk] = bb.x; bq1[kk] = bb.y;
            }
#pragma unroll
            for (int q = 0; q < 8; q++) {
                ull a[KBLK];
#pragma unroll
                for (int kk = 0; kk < KBLK; kk += 2) {
                    ulonglong2 av = *reinterpret_cast<const ulonglong2*>(
                        &As2[buf][ty * 8 + q][kb + kk]);
                    a[kk] = av.x; a[kk + 1] = av.y;
                }
#pragma unroll
                for (int cp = 0; cp < 2; cp++) {
                    ull pr = pmul(a[0], cp ? bq1[0] : bq0[0]);
#pragma unroll
                    for (int kk = 1; kk < KBLK; kk++)
                        pr = pfma(a[kk], cp ? bq1[kk] : bq0[kk], pr);
                    ull s = acc[q][cp];
                    ull t = padd(s, pr);
                    ull d = pfma(s, (ull)NEG1_PK, t);   // t - s  (exact)
                    ull e = pfma(d, (ull)NEG1_PK, pr);  // pr - d (exact)
                    acc[q][cp] = t;
                    cmp[q][cp] = padd(cmp[q][cp], e);
                }
            }
        }
    };

    if (PIPE) {
        load_tile(0);
        store_tile(0);
        __syncthreads();
        for (int ti = 0; ti < ntiles; ti++) {
            bool more = (ti + 1 < ntiles);
            if (more) load_tile(ti + 1);        // overlap global latency with compute
            compute(ti & 1);
            if (more) {
                store_tile((ti + 1) & 1);
                __syncthreads();
            }
        }
    } else {
        for (int ti = 0; ti < ntiles; ti++) {
            if (ti > 0) __syncthreads();        // protect buffer from prior compute
            load_tile(ti);
            store_tile(0);
            __syncthreads();
            compute(0);
        }
    }

#pragma unroll
    for (int q = 0; q < 8; q++) {
        int m = bm + ty * 8 + q;
#pragma unroll
        for (int cp = 0; cp < 2; cp++) {
            int n = bn + tx * 4 + cp * 2;
            float t0, t1, c0, c1;
            unpack2(acc[q][cp], t0, t1);
            unpack2(cmp[q][cp], c0, c1);
            if (n < N) {
                float v = __fadd_rn(__fsub_rn(t0, CBIAS), c0);
                Y[(size_t)m * N + n] = __fadd_rn(v, bias[n]);
            }
            if (n + 1 < N) {
                float v = __fadd_rn(__fsub_rn(t1, CBIAS), c1);
                Y[(size_t)m * N + n + 1] = __fadd_rn(v, bias[n + 1]);
            }
        }
    }
}

// ---------------------------------------------------------------------------
// LIF scan in fp64 (snntorch Leaky, reset='subtract'). Layout (B,T,C).
// ---------------------------------------------------------------------------
__global__ void lif_kernel(const float* __restrict__ Y, float* __restrict__ S, int C)
{
    int idx = blockIdx.x * blockDim.x + threadIdx.x;
    if (idx >= NB * C) return;
    int b = idx / C;
    int c = idx - b * C;
    const float* y = Y + (size_t)b * NT * C + c;
    float* s = S + (size_t)b * NT * C + c;
    double mem = 0.0;
#pragma unroll
    for (int t = 0; t < NT; t++) {
        double reset = (mem > 1.0) ? 1.0 : 0.0;
        mem = 0.95 * mem + (double)y[t * C] - reset;
        s[t * C] = (mem > 1.0) ? 1.0f : 0.0f;
    }
}

// Final LIF: layer-3 Y row stride 20. Emits spk3 (T,B,20) then mem3 (T,B,20).
__global__ void lif_out_kernel(const float* __restrict__ Y, float* __restrict__ out,
                               int out_size)
{
    int idx = blockIdx.x * blockDim.x + threadIdx.x;
    if (idx >= NB * 20) return;
    int b = idx / 20;
    int c = idx - b * 20;
    bool have_mem = (out_size >= 2 * NT * NB * 20);
    double mem = 0.0;
#pragma unroll
    for (int t = 0; t < NT; t++) {
        double reset = (mem > 1.0) ? 1.0 : 0.0;
        mem = 0.95 * mem + (double)Y[((size_t)b * NT + t) * 20 + c] - reset;
        float spk = (mem > 1.0) ? 1.0f : 0.0f;
        out[(size_t)t * NB * 20 + b * 20 + c] = spk;
        if (have_mem)
            out[(size_t)NT * NB * 20 + (size_t)t * NB * 20 + b * 20 + c] = (float)mem;
    }
}

// ---------------------------------------------------------------------------
extern "C" void kernel_launch(void* const* d_in, const int* in_sizes, int n_in,
                              void* d_out, int out_size)
{
    const float* data = (const float*)d_in[0];
    const float* W1   = (const float*)d_in[1];
    const float* b1   = (const float*)d_in[2];
    const float* P1   = (const float*)d_in[3];
    const float* SIG1 = (const float*)d_in[4];
    const float* g1   = (const float*)d_in[5];
    const float* be1  = (const float*)d_in[6];
    const float* mu1  = (const float*)d_in[7];
    const float* va1  = (const float*)d_in[8];
    const float* W2   = (const float*)d_in[9];
    const float* b2   = (const float*)d_in[10];
    const float* P2   = (const float*)d_in[11];
    const float* SIG2 = (const float*)d_in[12];
    const float* g2   = (const float*)d_in[13];
    const float* be2  = (const float*)d_in[14];
    const float* mu2  = (const float*)d_in[15];
    const float* va2  = (const float*)d_in[16];
    const float* W3   = (const float*)d_in[17];
    const float* b3   = (const float*)d_in[18];
    const float* P3   = (const float*)d_in[19];
    const float* SIG3 = (const float*)d_in[20];

    float *Wg1, *Wg2, *Wg3, *bb1, *bb2, *bb3, *Y, *S1, *S2, *Y3;
    cudaGetSymbolAddress((void**)&Wg1, g_Wg1);
    cudaGetSymbolAddress((void**)&Wg2, g_Wg2);
    cudaGetSymbolAddress((void**)&Wg3, g_Wg3);
    cudaGetSymbolAddress((void**)&bb1, g_bb1);
    cudaGetSymbolAddress((void**)&bb2, g_bb2);
    cudaGetSymbolAddress((void**)&bb3, g_bb3);
    cudaGetSymbolAddress((void**)&Y,   g_Y);
    cudaGetSymbolAddress((void**)&S1,  g_S1);
    cudaGetSymbolAddress((void**)&S2,  g_S2);
    cudaGetSymbolAddress((void**)&Y3,  g_Y3);

    // weight/bias prep (tiny). Layer-3 weights padded to 32 cols (zeros).
    zero_buf<<<(K2TOT * 32 + 255) / 256, 256>>>(Wg3, K2TOT * 32);
    prep_weights<<<(256 * 140 + 255) / 256, 256>>>(W1, P1, SIG1, g1, va1, Wg1, 256, 140, 256);
    prep_weights<<<(256 * 256 + 255) / 256, 256>>>(W2, P2, SIG2, g2, va2, Wg2, 256, 256, 256);
    prep_weights<<<(20 * 256 + 255) / 256, 256>>>(W3, P3, SIG3, nullptr, nullptr, Wg3, 20, 256, 32);
    prep_bias<<<1, 256>>>(b1, g1, be1, mu1, va1, bb1, 256);
    prep_bias<<<1, 256>>>(b2, g2, be2, mu2, va2, bb2, 256);
    prep_bias<<<1, 32>>>(b3, nullptr, nullptr, nullptr, nullptr, bb3, 20);

    // layer 1: dense inputs -> KBLK=8 chains, double-buffered
    conv_gemm_v11<128, 64, 8, true><<<dim3(200, 4), 256>>>(data, Wg1, bb1, Y, 256, 256, K1TOT, 140);
    lif_kernel<<<(NB * 256 + 255) / 256, 256>>>(Y, S1, 256);

    // layer 2: spike inputs -> KBLK=8 chains, double-buffered
    conv_gemm_v11<128, 64, 8, true><<<dim3(200, 4), 256>>>(S1, Wg2, bb2, Y, 256, 256, K2TOT, 256);
    lif_kernel<<<(NB * 256 + 255) / 256, 256>>>(Y, S2, 256);

    // layer 3: spike inputs, N=20 (weight rows padded to 32), single-buffered
    conv_gemm_v11<256, 32, 8, false><<<dim3(100, 1), 256>>>(S2, Wg3, bb3, Y3, 20, 32, K2TOT, 256);
    lif_out_kernel<<<(NB * 20 + 255) / 256, 256>>>(Y3, (float*)d_out, out_size);
}

// round 12
// speedup vs baseline: 1.3956x; 1.0126x over previous
#include <cuda_runtime.h>
#include <cstdint>

// SNN_Delay: 3x (DCLS gaussian 11-tap temporal conv -> [BN] -> LIF scan), forward only.
// Conv = implicit GEMM, biased FastTwoSum compensated accumulation on packed f32x2.
// R12: deferred compensation — product chains of 32 (carried across k-tile pairs in
//      registers, pr reset to +0 and pure-pfma chains), FastTwoSum every 2 tiles.
//      fma cost: 1.125 packed ops per packed MAC term (was 1.5).

typedef unsigned long long ull;

#define NT 25
#define NB 1024
#define MROWS (NB*NT)          // 25600
#define K1TOT (11*140)         // 1540
#define K2TOT (11*256)         // 2816

__device__ float g_Wg1[K1TOT*256];
__device__ float g_Wg2[K2TOT*256];
__device__ float g_Wg3[K2TOT*32];
__device__ float g_bb1[256];
__device__ float g_bb2[256];
__device__ float g_bb3[32];
__device__ float g_Y[MROWS*256];
__device__ float g_S1[MROWS*256];
__device__ float g_S2[MROWS*256];
__device__ float g_Y3[MROWS*20];

// ---------------------------------------------------------------------------
__global__ void prep_weights(const float* __restrict__ W, const float* __restrict__ P,
                             const float* __restrict__ SIG, const float* __restrict__ gamma,
                             const float* __restrict__ var, float* __restrict__ Wg,
                             int O, int I, int Ostride)
{
    int idx = blockIdx.x * blockDim.x + threadIdx.x;
    if (idx >= O * I) return;
    int o = idx / I;
    int i = idx - o * I;
    double pc = (double)P[idx] + 5.0;          // MAXD//2 = 5
    double s  = fabs((double)SIG[idx]) + 0.27;
    double g[11];
    double sum = 0.0;
#pragma unroll
    for (int j = 0; j < 11; j++) {
        double d = ((double)j - pc) / s;
        g[j] = exp(-0.5 * d * d);
        sum += g[j];
    }
    double scale = (double)W[idx] / (sum + 1e-7);
    if (gamma) scale *= (double)gamma[o] / sqrt((double)var[o] + 1e-5);
#pragma unroll
    for (int j = 0; j < 11; j++)
        Wg[(size_t)(j * I + i) * Ostride + o] = (float)(g[j] * scale);
}

__global__ void zero_buf(float* p, int n)
{
    int i = blockIdx.x * blockDim.x + threadIdx.x;
    if (i < n) p[i] = 0.f;
}

__global__ void prep_bias(const float* __restrict__ b, const float* __restrict__ gamma,
                          const float* __restrict__ beta, const float* __restrict__ mean,
                          const float* __restrict__ var, float* __restrict__ out, int O)
{
    int o = blockIdx.x * blockDim.x + threadIdx.x;
    if (o >= O) return;
    double v = (double)b[o];
    if (gamma) {
        double sc = (double)gamma[o] / sqrt((double)var[o] + 1e-5);
        v = (v - (double)mean[o]) * sc + (double)beta[o];
    }
    out[o] = (float)v;
}

// ---------------------------------------------------------------------------
// packed f32x2 helpers
// ---------------------------------------------------------------------------
__device__ __forceinline__ ull pack2s(float a) {
    ull r; asm("mov.b64 %0, {%1,%1};" : "=l"(r) : "f"(a)); return r;
}
__device__ __forceinline__ void unpack2(ull v, float& x, float& y) {
    asm("mov.b64 {%0,%1}, %2;" : "=f"(x), "=f"(y) : "l"(v));
}
__device__ __forceinline__ ull padd(ull a, ull b) {
    ull r; asm("add.rn.f32x2 %0, %1, %2;" : "=l"(r) : "l"(a), "l"(b)); return r;
}
__device__ __forceinline__ ull pfma(ull a, ull b, ull c) {
    ull r; asm("fma.rn.f32x2 %0, %1, %2, %3;" : "=l"(r) : "l"(a), "l"(b), "l"(c)); return r;
}

#define NEG1_PK  0xBF800000BF800000ULL   // (-1.f, -1.f)
#define CBIAS    512.0f
#define CBIAS_PK 0x4400000044000000ULL   // (512.f, 512.f)

// ---------------------------------------------------------------------------
// Implicit-GEMM conv, biased FastTwoSum compensated accumulation, packed f32x2.
// Accumulator lanes = two adjacent N columns; A broadcast from duplicated smem.
// C[m,n] = sum_k U[m,k]*Wg[k,n] + bias[n],
//   U[m,k] = X[(m-10)*I + k] if k >= (10 - m%25)*I else 0.
// Wg rows stride Nw (padded); Y rows stride N.
// Product chains run across 2 k-tiles (32 terms) in registers (pr); FastTwoSum
// applied every second tile and at the last tile. pr reset to +0 packed.
// PIPE: ping-pong double-buffered smem with global prefetch (1 sync/tile).
// ---------------------------------------------------------------------------
template<int BM, int BN, bool PIPE>
__global__ void __launch_bounds__(256)
conv_gemm_v12(const float* __restrict__ X, const float* __restrict__ Wg,
              const float* __restrict__ bias, float* __restrict__ Y,
              int N, int Nw, int Ktot, int I)
{
    constexpr int NBUF  = PIPE ? 2 : 1;
    constexpr int APASS = BM / 64;       // row passes for A loads
    constexpr int CG    = BN / 4;        // col groups
    static_assert(256 / CG * 8 == BM, "compute map covers BM");
    __shared__ ull   As2[NBUF][BM][18];  // dup (a,a); [row][kk]
    __shared__ float Bs[NBUF][16][BN + 4];

    const int tid = threadIdx.x;
    const int bm = blockIdx.x * BM;
    const int bn = blockIdx.y * BN;

    // A-load geometry
    const int arow = tid >> 2;          // 0..63
    const int akq  = (tid & 3) * 4;     // 0,4,8,12
    long abase[APASS];
    int  alow[APASS];
#pragma unroll
    for (int r = 0; r < APASS; r++) {
        int m = bm + arow + r * 64;
        int t = m % 25;
        abase[r] = (long)(m - 10) * I;
        alow[r]  = (t < 10) ? (10 - t) * I : 0;   // multiple of 4 (I%4==0)
    }
    // B-load geometry
    const int bkrow = tid / CG;          // k-row
    const int bcq   = (tid % CG) * 4;    // col offset

    ull acc[8][2], cmp[8][2], pr[8][2];  // [row q][col pair]
#pragma unroll
    for (int q = 0; q < 8; q++) {
        acc[q][0] = CBIAS_PK; acc[q][1] = CBIAS_PK;
        cmp[q][0] = 0ull;     cmp[q][1] = 0ull;
        pr[q][0]  = 0ull;     pr[q][1]  = 0ull;   // +0.0 packed
    }

    const int ty = tid / CG;            // 8-row group
    const int tx = tid % CG;            // 4-col group

    const int ntiles = (Ktot + 15) / 16;

    float4 va[APASS];
    float4 vb = make_float4(0.f, 0.f, 0.f, 0.f);

    auto load_tile = [&](int ti) {
        int k0 = ti * 16;
#pragma unroll
        for (int r = 0; r < APASS; r++) {
            int k = k0 + akq;
            va[r] = make_float4(0.f, 0.f, 0.f, 0.f);
            if (k >= alow[r] && k < Ktot)       // Ktot%4==0 -> vector-exact
                va[r] = *reinterpret_cast<const float4*>(X + abase[r] + k);
        }
        if (bkrow < 16) {
            int k = k0 + bkrow;
            vb = make_float4(0.f, 0.f, 0.f, 0.f);
            if (k < Ktot)
                vb = *reinterpret_cast<const float4*>(Wg + (size_t)k * Nw + bn + bcq);
        }
    };
    auto store_tile = [&](int buf) {
#pragma unroll
        for (int r = 0; r < APASS; r++) {
            int row = arow + r * 64;
            ulonglong2 w0; w0.x = pack2s(va[r].x); w0.y = pack2s(va[r].y);
            ulonglong2 w1; w1.x = pack2s(va[r].z); w1.y = pack2s(va[r].w);
            *reinterpret_cast<ulonglong2*>(&As2[buf][row][akq])     = w0;
            *reinterpret_cast<ulonglong2*>(&As2[buf][row][akq + 2]) = w1;
        }
        if (bkrow < 16)
            *reinterpret_cast<float4*>(&Bs[buf][bkrow][bcq]) = vb;
    };
    auto compute = [&](int buf, bool do_comp) {
#pragma unroll
        for (int kb = 0; kb < 16; kb += 8) {
            ull bq0[8], bq1[8];
#pragma unroll
            for (int kk = 0; kk < 8; kk++) {
                ulonglong2 bb = *reinterpret_cast<const ulonglong2*>(
                    &Bs[buf][kb + kk][tx * 4]);
                bq0[kk] = bb.x; bq1[kk] = bb.y;
            }
#pragma unroll
            for (int q = 0; q < 8; q++) {
                ull a[8];
#pragma unroll
                for (int kk = 0; kk < 8; kk += 2) {
                    ulonglong2 av = *reinterpret_cast<const ulonglong2*>(
                        &As2[buf][ty * 8 + q][kb + kk]);
                    a[kk] = av.x; a[kk + 1] = av.y;
                }
#pragma unroll
                for (int cp = 0; cp < 2; cp++) {
                    ull p = pr[q][cp];
#pragma unroll
                    for (int kk = 0; kk < 8; kk++)
                        p = pfma(a[kk], cp ? bq1[kk] : bq0[kk], p);
                    pr[q][cp] = p;
                }
            }
        }
        if (do_comp) {
#pragma unroll
            for (int q = 0; q < 8; q++) {
#pragma unroll
                for (int cp = 0; cp < 2; cp++) {
                    ull p = pr[q][cp];
                    ull s = acc[q][cp];
                    ull t = padd(s, p);
                    ull d = pfma(s, (ull)NEG1_PK, t);   // t - s  (exact)
                    ull e = pfma(d, (ull)NEG1_PK, p);   // p - d  (exact)
                    acc[q][cp] = t;
                    cmp[q][cp] = padd(cmp[q][cp], e);
                    pr[q][cp]  = 0ull;                  // restart chain at +0
                }
            }
        }
    };

    if (PIPE) {
        load_tile(0);
        store_tile(0);
        __syncthreads();
        for (int ti = 0; ti < ntiles; ti++) {
            bool more = (ti + 1 < ntiles);
            if (more) load_tile(ti + 1);        // overlap global latency with compute
            compute(ti & 1, (ti & 1) || !more);
            if (more) {
                store_tile((ti + 1) & 1);
                __syncthreads();
            }
        }
    } else {
        for (int ti = 0; ti < ntiles; ti++) {
            if (ti > 0) __syncthreads();        // protect buffer from prior compute
            load_tile(ti);
            store_tile(0);
            __syncthreads();
            compute(0, (ti & 1) || (ti == ntiles - 1));
        }
    }

#pragma unroll
    for (int q = 0; q < 8; q++) {
        int m = bm + ty * 8 + q;
#pragma unroll
        for (int cp = 0; cp < 2; cp++) {
            int n = bn + tx * 4 + cp * 2;
            float t0, t1, c0, c1;
            unpack2(acc[q][cp], t0, t1);
            unpack2(cmp[q][cp], c0, c1);
            if (n < N) {
                float v = __fadd_rn(__fsub_rn(t0, CBIAS), c0);
                Y[(size_t)m * N + n] = __fadd_rn(v, bias[n]);
            }
            if (n + 1 < N) {
                float v = __fadd_rn(__fsub_rn(t1, CBIAS), c1);
                Y[(size_t)m * N + n + 1] = __fadd_rn(v, bias[n + 1]);
            }
        }
    }
}

// ---------------------------------------------------------------------------
// LIF scan in fp64 (snntorch Leaky, reset='subtract'). Layout (B,T,C).
// ---------------------------------------------------------------------------
__global__ void lif_kernel(const float* __restrict__ Y, float* __restrict__ S, int C)
{
    int idx = blockIdx.x * blockDim.x + threadIdx.x;
    if (idx >= NB * C) return;
    int b = idx / C;
    int c = idx - b * C;
    const float* y = Y + (size_t)b * NT * C + c;
    float* s = S + (size_t)b * NT * C + c;
    double mem = 0.0;
#pragma unroll
    for (int t = 0; t < NT; t++) {
        double reset = (mem > 1.0) ? 1.0 : 0.0;
        mem = 0.95 * mem + (double)y[t * C] - reset;
        s[t * C] = (mem > 1.0) ? 1.0f : 0.0f;
    }
}

// Final LIF: layer-3 Y row stride 20. Emits spk3 (T,B,20) then mem3 (T,B,20).
__global__ void lif_out_kernel(const float* __restrict__ Y, float* __restrict__ out,
                               int out_size)
{
    int idx = blockIdx.x * blockDim.x + threadIdx.x;
    if (idx >= NB * 20) return;
    int b = idx / 20;
    int c = idx - b * 20;
    bool have_mem = (out_size >= 2 * NT * NB * 20);
    double mem = 0.0;
#pragma unroll
    for (int t = 0; t < NT; t++) {
        double reset = (mem > 1.0) ? 1.0 : 0.0;
        mem = 0.95 * mem + (double)Y[((size_t)b * NT + t) * 20 + c] - reset;
        float spk = (mem > 1.0) ? 1.0f : 0.0f;
        out[(size_t)t * NB * 20 + b * 20 + c] = spk;
        if (have_mem)
            out[(size_t)NT * NB * 20 + (size_t)t * NB * 20 + b * 20 + c] = (float)mem;
    }
}

// ---------------------------------------------------------------------------
extern "C" void kernel_launch(void* const* d_in, const int* in_sizes, int n_in,
                              void* d_out, int out_size)
{
    const float* data = (const float*)d_in[0];
    const float* W1   = (const float*)d_in[1];
    const float* b1   = (const float*)d_in[2];
    const float* P1   = (const float*)d_in[3];
    const float* SIG1 = (const float*)d_in[4];
    const float* g1   = (const float*)d_in[5];
    const float* be1  = (const float*)d_in[6];
    const float* mu1  = (const float*)d_in[7];
    const float* va1  = (const float*)d_in[8];
    const float* W2   = (const float*)d_in[9];
    const float* b2   = (const float*)d_in[10];
    const float* P2   = (const float*)d_in[11];
    const float* SIG2 = (const float*)d_in[12];
    const float* g2   = (const float*)d_in[13];
    const float* be2  = (const float*)d_in[14];
    const float* mu2  = (const float*)d_in[15];
    const float* va2  = (const float*)d_in[16];
    const float* W3   = (const float*)d_in[17];
    const float* b3   = (const float*)d_in[18];
    const float* P3   = (const float*)d_in[19];
    const float* SIG3 = (const float*)d_in[20];

    float *Wg1, *Wg2, *Wg3, *bb1, *bb2, *bb3, *Y, *S1, *S2, *Y3;
    cudaGetSymbolAddress((void**)&Wg1, g_Wg1);
    cudaGetSymbolAddress((void**)&Wg2, g_Wg2);
    cudaGetSymbolAddress((void**)&Wg3, g_Wg3);
    cudaGetSymbolAddress((void**)&bb1, g_bb1);
    cudaGetSymbolAddress((void**)&bb2, g_bb2);
    cudaGetSymbolAddress((void**)&bb3, g_bb3);
    cudaGetSymbolAddress((void**)&Y,   g_Y);
    cudaGetSymbolAddress((void**)&S1,  g_S1);
    cudaGetSymbolAddress((void**)&S2,  g_S2);
    cudaGetSymbolAddress((void**)&Y3,  g_Y3);

    // weight/bias prep (tiny). Layer-3 weights padded to 32 cols (zeros).
    zero_buf<<<(K2TOT * 32 + 255) / 256, 256>>>(Wg3, K2TOT * 32);
    prep_weights<<<(256 * 140 + 255) / 256, 256>>>(W1, P1, SIG1, g1, va1, Wg1, 256, 140, 256);
    prep_weights<<<(256 * 256 + 255) / 256, 256>>>(W2, P2, SIG2, g2, va2, Wg2, 256, 256, 256);
    prep_weights<<<(20 * 256 + 255) / 256, 256>>>(W3, P3, SIG3, nullptr, nullptr, Wg3, 20, 256, 32);
    prep_bias<<<1, 256>>>(b1, g1, be1, mu1, va1, bb1, 256);
    prep_bias<<<1, 256>>>(b2, g2, be2, mu2, va2, bb2, 256);
    prep_bias<<<1, 32>>>(b3, nullptr, nullptr, nullptr, nullptr, bb3, 20);

    // layer 1: dense inputs, double-buffered
    conv_gemm_v12<128, 64, true><<<dim3(200, 4), 256>>>(data, Wg1, bb1, Y, 256, 256, K1TOT, 140);
    lif_kernel<<<(NB * 256 + 255) / 256, 256>>>(Y, S1, 256);

    // layer 2: spike inputs, double-buffered
    conv_gemm_v12<128, 64, true><<<dim3(200, 4), 256>>>(S1, Wg2, bb2, Y, 256, 256, K2TOT, 256);
    lif_kernel<<<(NB * 256 + 255) / 256, 256>>>(Y, S2, 256);

    // layer 3: spike inputs, N=20 (weight rows padded to 32), single-buffered
    conv_gemm_v12<256, 32, false><<<dim3(100, 1), 256>>>(S2, Wg3, bb3, Y3, 20, 32, K2TOT, 256);
    lif_out_kernel<<<(NB * 20 + 255) / 256, 256>>>(Y3, (float*)d_out, out_size);
}

// round 13
// speedup vs baseline: 1.4675x; 1.0516x over previous
#include <cuda_runtime.h>
#include <cstdint>

// SNN_Delay: 3x (DCLS gaussian 11-tap temporal conv -> [BN] -> LIF scan), forward only.
// Conv = implicit GEMM, biased FastTwoSum compensated accumulation on packed f32x2,
// product chains of 32 terms carried across k-tile pairs (comp every 2 tiles).
// R13: 512-thread CTAs with 4-row microtile (regs ~100 -> 4 warps/SMSP latency hiding).
//      Arithmetic per output is BIT-IDENTICAL to R12 (chain order preserved).

typedef unsigned long long ull;

#define NT 25
#define NB 1024
#define MROWS (NB*NT)          // 25600
#define K1TOT (11*140)         // 1540
#define K2TOT (11*256)         // 2816

__device__ float g_Wg1[K1TOT*256];
__device__ float g_Wg2[K2TOT*256];
__device__ float g_Wg3[K2TOT*32];
__device__ float g_bb1[256];
__device__ float g_bb2[256];
__device__ float g_bb3[32];
__device__ float g_Y[MROWS*256];
__device__ float g_S1[MROWS*256];
__device__ float g_S2[MROWS*256];
__device__ float g_Y3[MROWS*20];

// ---------------------------------------------------------------------------
__global__ void prep_weights(const float* __restrict__ W, const float* __restrict__ P,
                             const float* __restrict__ SIG, const float* __restrict__ gamma,
                             const float* __restrict__ var, float* __restrict__ Wg,
                             int O, int I, int Ostride)
{
    int idx = blockIdx.x * blockDim.x + threadIdx.x;
    if (idx >= O * I) return;
    int o = idx / I;
    int i = idx - o * I;
    double pc = (double)P[idx] + 5.0;          // MAXD//2 = 5
    double s  = fabs((double)SIG[idx]) + 0.27;
    double g[11];
    double sum = 0.0;
#pragma unroll
    for (int j = 0; j < 11; j++) {
        double d = ((double)j - pc) / s;
        g[j] = exp(-0.5 * d * d);
        sum += g[j];
    }
    double scale = (double)W[idx] / (sum + 1e-7);
    if (gamma) scale *= (double)gamma[o] / sqrt((double)var[o] + 1e-5);
#pragma unroll
    for (int j = 0; j < 11; j++)
        Wg[(size_t)(j * I + i) * Ostride + o] = (float)(g[j] * scale);
}

__global__ void zero_buf(float* p, int n)
{
    int i = blockIdx.x * blockDim.x + threadIdx.x;
    if (i < n) p[i] = 0.f;
}

__global__ void prep_bias(const float* __restrict__ b, const float* __restrict__ gamma,
                          const float* __restrict__ beta, const float* __restrict__ mean,
                          const float* __restrict__ var, float* __restrict__ out, int O)
{
    int o = blockIdx.x * blockDim.x + threadIdx.x;
    if (o >= O) return;
    double v = (double)b[o];
    if (gamma) {
        double sc = (double)gamma[o] / sqrt((double)var[o] + 1e-5);
        v = (v - (double)mean[o]) * sc + (double)beta[o];
    }
    out[o] = (float)v;
}

// ---------------------------------------------------------------------------
// packed f32x2 helpers
// ---------------------------------------------------------------------------
__device__ __forceinline__ ull pack2s(float a) {
    ull r; asm("mov.b64 %0, {%1,%1};" : "=l"(r) : "f"(a)); return r;
}
__device__ __forceinline__ void unpack2(ull v, float& x, float& y) {
    asm("mov.b64 {%0,%1}, %2;" : "=f"(x), "=f"(y) : "l"(v));
}
__device__ __forceinline__ ull padd(ull a, ull b) {
    ull r; asm("add.rn.f32x2 %0, %1, %2;" : "=l"(r) : "l"(a), "l"(b)); return r;
}
__device__ __forceinline__ ull pfma(ull a, ull b, ull c) {
    ull r; asm("fma.rn.f32x2 %0, %1, %2, %3;" : "=l"(r) : "l"(a), "l"(b), "l"(c)); return r;
}

#define NEG1_PK  0xBF800000BF800000ULL   // (-1.f, -1.f)
#define CBIAS    512.0f
#define CBIAS_PK 0x4400000044000000ULL   // (512.f, 512.f)

// ---------------------------------------------------------------------------
// Implicit-GEMM conv. 512 threads, microtile 4 rows x 4 cols (2 packed pairs).
// C[m,n] = sum_k U[m,k]*Wg[k,n] + bias[n],
//   U[m,k] = X[(m-10)*I + k] if k >= (10 - m%25)*I else 0.
// Product chain pr carried across sub-chunks of 4 and across 2 k-tiles (32 terms);
// biased FastTwoSum at every second tile and the last tile (same order as R12).
// PIPE: ping-pong double-buffered smem with global prefetch (1 sync/tile).
// ---------------------------------------------------------------------------
template<int BM, int BN, bool PIPE>
__global__ void __launch_bounds__(512)
conv_gemm_v13(const float* __restrict__ X, const float* __restrict__ Wg,
              const float* __restrict__ bias, float* __restrict__ Y,
              int N, int Nw, int Ktot, int I)
{
    constexpr int NBUF  = PIPE ? 2 : 1;
    constexpr int APASS = BM / 128;      // A-load row passes (512 thr, 1 float4 each)
    constexpr int CG    = BN / 4;        // col groups
    static_assert(512 / CG * 4 == BM, "compute map covers BM");
    __shared__ ull   As2[NBUF][BM][18];  // dup (a,a); [row][kk]
    __shared__ float Bs[NBUF][16][BN + 4];

    const int tid = threadIdx.x;
    const int bm = blockIdx.x * BM;
    const int bn = blockIdx.y * BN;

    // A-load geometry: rows arow + r*128, one float4 of k each
    const int arow = tid >> 2;          // 0..127
    const int akq  = (tid & 3) * 4;     // 0,4,8,12
    long abase[APASS];
    int  alow[APASS];
#pragma unroll
    for (int r = 0; r < APASS; r++) {
        int m = bm + arow + r * 128;
        int t = m % 25;
        abase[r] = (long)(m - 10) * I;
        alow[r]  = (t < 10) ? (10 - t) * I : 0;   // multiple of 4 (I%4==0)
    }
    // B-load geometry
    const int bkrow = tid / CG;          // k-row
    const int bcq   = (tid % CG) * 4;    // col offset

    ull acc[4][2], cmp[4][2], pr[4][2];  // [row q][col pair]
#pragma unroll
    for (int q = 0; q < 4; q++) {
        acc[q][0] = CBIAS_PK; acc[q][1] = CBIAS_PK;
        cmp[q][0] = 0ull;     cmp[q][1] = 0ull;
        pr[q][0]  = 0ull;     pr[q][1]  = 0ull;   // +0.0 packed
    }

    const int ty = tid / CG;            // 4-row group
    const int tx = tid % CG;            // 4-col group

    const int ntiles = (Ktot + 15) / 16;

    float4 va[APASS];
    float4 vb = make_float4(0.f, 0.f, 0.f, 0.f);

    auto load_tile = [&](int ti) {
        int k0 = ti * 16;
#pragma unroll
        for (int r = 0; r < APASS; r++) {
            int k = k0 + akq;
            va[r] = make_float4(0.f, 0.f, 0.f, 0.f);
            if (k >= alow[r] && k < Ktot)       // Ktot%4==0 -> vector-exact
                va[r] = *reinterpret_cast<const float4*>(X + abase[r] + k);
        }
        if (bkrow < 16) {
            int k = k0 + bkrow;
            vb = make_float4(0.f, 0.f, 0.f, 0.f);
            if (k < Ktot)
                vb = *reinterpret_cast<const float4*>(Wg + (size_t)k * Nw + bn + bcq);
        }
    };
    auto store_tile = [&](int buf) {
#pragma unroll
        for (int r = 0; r < APASS; r++) {
            int row = arow + r * 128;
            ulonglong2 w0; w0.x = pack2s(va[r].x); w0.y = pack2s(va[r].y);
            ulonglong2 w1; w1.x = pack2s(va[r].z); w1.y = pack2s(va[r].w);
            *reinterpret_cast<ulonglong2*>(&As2[buf][row][akq])     = w0;
            *reinterpret_cast<ulonglong2*>(&As2[buf][row][akq + 2]) = w1;
        }
        if (bkrow < 16)
            *reinterpret_cast<float4*>(&Bs[buf][bkrow][bcq]) = vb;
    };
    auto compute = [&](int buf, bool do_comp) {
#pragma unroll
        for (int kb = 0; kb < 16; kb += 4) {
            ull bq0[4], bq1[4];
#pragma unroll
            for (int kk = 0; kk < 4; kk++) {
                ulonglong2 bb = *reinterpret_cast<const ulonglong2*>(
                    &Bs[buf][kb + kk][tx * 4]);
                bq0[kk] = bb.x; bq1[kk] = bb.y;
            }
#pragma unroll
            for (int q = 0; q < 4; q++) {
                ull a[4];
#pragma unroll
                for (int kk = 0; kk < 4; kk += 2) {
                    ulonglong2 av = *reinterpret_cast<const ulonglong2*>(
                        &As2[buf][ty * 4 + q][kb + kk]);
                    a[kk] = av.x; a[kk + 1] = av.y;
                }
#pragma unroll
                for (int cp = 0; cp < 2; cp++) {
                    ull p = pr[q][cp];
#pragma unroll
                    for (int kk = 0; kk < 4; kk++)
                        p = pfma(a[kk], cp ? bq1[kk] : bq0[kk], p);
                    pr[q][cp] = p;
                }
            }
        }
        if (do_comp) {
#pragma unroll
            for (int q = 0; q < 4; q++) {
#pragma unroll
                for (int cp = 0; cp < 2; cp++) {
                    ull p = pr[q][cp];
                    ull s = acc[q][cp];
                    ull t = padd(s, p);
                    ull d = pfma(s, (ull)NEG1_PK, t);   // t - s  (exact)
                    ull e = pfma(d, (ull)NEG1_PK, p);   // p - d  (exact)
                    acc[q][cp] = t;
                    cmp[q][cp] = padd(cmp[q][cp], e);
                    pr[q][cp]  = 0ull;                  // restart chain at +0
                }
            }
        }
    };

    if (PIPE) {
        load_tile(0);
        store_tile(0);
        __syncthreads();
        for (int ti = 0; ti < ntiles; ti++) {
            bool more = (ti + 1 < ntiles);
            if (more) load_tile(ti + 1);        // overlap global latency with compute
            compute(ti & 1, (ti & 1) || !more);
            if (more) {
                store_tile((ti + 1) & 1);
                __syncthreads();
            }
        }
    } else {
        for (int ti = 0; ti < ntiles; ti++) {
            if (ti > 0) __syncthreads();        // protect buffer from prior compute
            load_tile(ti);
            store_tile(0);
            __syncthreads();
            compute(0, (ti & 1) || (ti == ntiles - 1));
        }
    }

#pragma unroll
    for (int q = 0; q < 4; q++) {
        int m = bm + ty * 4 + q;
#pragma unroll
        for (int cp = 0; cp < 2; cp++) {
            int n = bn + tx * 4 + cp * 2;
            float t0, t1, c0, c1;
            unpack2(acc[q][cp], t0, t1);
            unpack2(cmp[q][cp], c0, c1);
            if (n < N) {
                float v = __fadd_rn(__fsub_rn(t0, CBIAS), c0);
                Y[(size_t)m * N + n] = __fadd_rn(v, bias[n]);
            }
            if (n + 1 < N) {
                float v = __fadd_rn(__fsub_rn(t1, CBIAS), c1);
                Y[(size_t)m * N + n + 1] = __fadd_rn(v, bias[n + 1]);
            }
        }
    }
}

// ---------------------------------------------------------------------------
// LIF scan in fp64 (snntorch Leaky, reset='subtract'). Layout (B,T,C).
// ---------------------------------------------------------------------------
__global__ void lif_kernel(const float* __restrict__ Y, float* __restrict__ S, int C)
{
    int idx = blockIdx.x * blockDim.x + threadIdx.x;
    if (idx >= NB * C) return;
    int b = idx / C;
    int c = idx - b * C;
    const float* y = Y + (size_t)b * NT * C + c;
    float* s = S + (size_t)b * NT * C + c;
    double mem = 0.0;
#pragma unroll
    for (int t = 0; t < NT; t++) {
        double reset = (mem > 1.0) ? 1.0 : 0.0;
        mem = 0.95 * mem + (double)y[t * C] - reset;
        s[t * C] = (mem > 1.0) ? 1.0f : 0.0f;
    }
}

// Final LIF: layer-3 Y row stride 20. Emits spk3 (T,B,20) then mem3 (T,B,20).
__global__ void lif_out_kernel(const float* __restrict__ Y, float* __restrict__ out,
                               int out_size)
{
    int idx = blockIdx.x * blockDim.x + threadIdx.x;
    if (idx >= NB * 20) return;
    int b = idx / 20;
    int c = idx - b * 20;
    bool have_mem = (out_size >= 2 * NT * NB * 20);
    double mem = 0.0;
#pragma unroll
    for (int t = 0; t < NT; t++) {
        double reset = (mem > 1.0) ? 1.0 : 0.0;
        mem = 0.95 * mem + (double)Y[((size_t)b * NT + t) * 20 + c] - reset;
        float spk = (mem > 1.0) ? 1.0f : 0.0f;
        out[(size_t)t * NB * 20 + b * 20 + c] = spk;
        if (have_mem)
            out[(size_t)NT * NB * 20 + (size_t)t * NB * 20 + b * 20 + c] = (float)mem;
    }
}

// ---------------------------------------------------------------------------
extern "C" void kernel_launch(void* const* d_in, const int* in_sizes, int n_in,
                              void* d_out, int out_size)
{
    const float* data = (const float*)d_in[0];
    const float* W1   = (const float*)d_in[1];
    const float* b1   = (const float*)d_in[2];
    const float* P1   = (const float*)d_in[3];
    const float* SIG1 = (const float*)d_in[4];
    const float* g1   = (const float*)d_in[5];
    const float* be1  = (const float*)d_in[6];
    const float* mu1  = (const float*)d_in[7];
    const float* va1  = (const float*)d_in[8];
    const float* W2   = (const float*)d_in[9];
    const float* b2   = (const float*)d_in[10];
    const float* P2   = (const float*)d_in[11];
    const float* SIG2 = (const float*)d_in[12];
    const float* g2   = (const float*)d_in[13];
    const float* be2  = (const float*)d_in[14];
    const float* mu2  = (const float*)d_in[15];
    const float* va2  = (const float*)d_in[16];
    const float* W3   = (const float*)d_in[17];
    const float* b3   = (const float*)d_in[18];
    const float* P3   = (const float*)d_in[19];
    const float* SIG3 = (const float*)d_in[20];

    float *Wg1, *Wg2, *Wg3, *bb1, *bb2, *bb3, *Y, *S1, *S2, *Y3;
    cudaGetSymbolAddress((void**)&Wg1, g_Wg1);
    cudaGetSymbolAddress((void**)&Wg2, g_Wg2);
    cudaGetSymbolAddress((void**)&Wg3, g_Wg3);
    cudaGetSymbolAddress((void**)&bb1, g_bb1);
    cudaGetSymbolAddress((void**)&bb2, g_bb2);
    cudaGetSymbolAddress((void**)&bb3, g_bb3);
    cudaGetSymbolAddress((void**)&Y,   g_Y);
    cudaGetSymbolAddress((void**)&S1,  g_S1);
    cudaGetSymbolAddress((void**)&S2,  g_S2);
    cudaGetSymbolAddress((void**)&Y3,  g_Y3);

    // weight/bias prep (tiny). Layer-3 weights padded to 32 cols (zeros).
    zero_buf<<<(K2TOT * 32 + 255) / 256, 256>>>(Wg3, K2TOT * 32);
    prep_weights<<<(256 * 140 + 255) / 256, 256>>>(W1, P1, SIG1, g1, va1, Wg1, 256, 140, 256);
    prep_weights<<<(256 * 256 + 255) / 256, 256>>>(W2, P2, SIG2, g2, va2, Wg2, 256, 256, 256);
    prep_weights<<<(20 * 256 + 255) / 256, 256>>>(W3, P3, SIG3, nullptr, nullptr, Wg3, 20, 256, 32);
    prep_bias<<<1, 256>>>(b1, g1, be1, mu1, va1, bb1, 256);
    prep_bias<<<1, 256>>>(b2, g2, be2, mu2, va2, bb2, 256);
    prep_bias<<<1, 32>>>(b3, nullptr, nullptr, nullptr, nullptr, bb3, 20);

    // layer 1: dense inputs, double-buffered
    conv_gemm_v13<128, 64, true><<<dim3(200, 4), 512>>>(data, Wg1, bb1, Y, 256, 256, K1TOT, 140);
    lif_kernel<<<(NB * 256 + 255) / 256, 256>>>(Y, S1, 256);

    // layer 2: spike inputs, double-buffered
    conv_gemm_v13<128, 64, true><<<dim3(200, 4), 512>>>(S1, Wg2, bb2, Y, 256, 256, K2TOT, 256);
    lif_kernel<<<(NB * 256 + 255) / 256, 256>>>(Y, S2, 256);

    // layer 3: spike inputs, N=20 (weight rows padded to 32), single-buffered
    conv_gemm_v13<256, 32, false><<<dim3(100, 1), 512>>>(S2, Wg3, bb3, Y3, 20, 32, K2TOT, 256);
    lif_out_kernel<<<(NB * 20 + 255) / 256, 256>>>(Y3, (float*)d_out, out_size);
}

// round 14
// speedup vs baseline: 1.6321x; 1.1121x over previous
#include <cuda_runtime.h>
#include <cstdint>

// SNN_Delay: 3x (DCLS gaussian 11-tap temporal conv -> [BN] -> LIF scan), forward only.
// Conv = implicit GEMM, biased FastTwoSum compensated accumulation on packed f32x2,
// product chains of 64 terms carried across 4 k-tiles, comp every 4th tile.
// R14: 256-thread CTAs (BM=64/BN=64; L3 BM=128/BN=32) -> 2 CTAs/SM, independent
//      barriers decouple sync stalls. L3 double-buffered too.

typedef unsigned long long ull;

#define NT 25
#define NB 1024
#define MROWS (NB*NT)          // 25600
#define K1TOT (11*140)         // 1540
#define K2TOT (11*256)         // 2816

__device__ float g_Wg1[K1TOT*256];
__device__ float g_Wg2[K2TOT*256];
__device__ float g_Wg3[K2TOT*32];
__device__ float g_bb1[256];
__device__ float g_bb2[256];
__device__ float g_bb3[32];
__device__ float g_Y[MROWS*256];
__device__ float g_S1[MROWS*256];
__device__ float g_S2[MROWS*256];
__device__ float g_Y3[MROWS*20];

// ---------------------------------------------------------------------------
__global__ void prep_weights(const float* __restrict__ W, const float* __restrict__ P,
                             const float* __restrict__ SIG, const float* __restrict__ gamma,
                             const float* __restrict__ var, float* __restrict__ Wg,
                             int O, int I, int Ostride)
{
    int idx = blockIdx.x * blockDim.x + threadIdx.x;
    if (idx >= O * I) return;
    int o = idx / I;
    int i = idx - o * I;
    double pc = (double)P[idx] + 5.0;          // MAXD//2 = 5
    double s  = fabs((double)SIG[idx]) + 0.27;
    double g[11];
    double sum = 0.0;
#pragma unroll
    for (int j = 0; j < 11; j++) {
        double d = ((double)j - pc) / s;
        g[j] = exp(-0.5 * d * d);
        sum += g[j];
    }
    double scale = (double)W[idx] / (sum + 1e-7);
    if (gamma) scale *= (double)gamma[o] / sqrt((double)var[o] + 1e-5);
#pragma unroll
    for (int j = 0; j < 11; j++)
        Wg[(size_t)(j * I + i) * Ostride + o] = (float)(g[j] * scale);
}

__global__ void zero_buf(float* p, int n)
{
    int i = blockIdx.x * blockDim.x + threadIdx.x;
    if (i < n) p[i] = 0.f;
}

__global__ void prep_bias(const float* __restrict__ b, const float* __restrict__ gamma,
                          const float* __restrict__ beta, const float* __restrict__ mean,
                          const float* __restrict__ var, float* __restrict__ out, int O)
{
    int o = blockIdx.x * blockDim.x + threadIdx.x;
    if (o >= O) return;
    double v = (double)b[o];
    if (gamma) {
        double sc = (double)gamma[o] / sqrt((double)var[o] + 1e-5);
        v = (v - (double)mean[o]) * sc + (double)beta[o];
    }
    out[o] = (float)v;
}

// ---------------------------------------------------------------------------
// packed f32x2 helpers
// ---------------------------------------------------------------------------
__device__ __forceinline__ ull pack2s(float a) {
    ull r; asm("mov.b64 %0, {%1,%1};" : "=l"(r) : "f"(a)); return r;
}
__device__ __forceinline__ void unpack2(ull v, float& x, float& y) {
    asm("mov.b64 {%0,%1}, %2;" : "=f"(x), "=f"(y) : "l"(v));
}
__device__ __forceinline__ ull padd(ull a, ull b) {
    ull r; asm("add.rn.f32x2 %0, %1, %2;" : "=l"(r) : "l"(a), "l"(b)); return r;
}
__device__ __forceinline__ ull pfma(ull a, ull b, ull c) {
    ull r; asm("fma.rn.f32x2 %0, %1, %2, %3;" : "=l"(r) : "l"(a), "l"(b), "l"(c)); return r;
}

#define NEG1_PK  0xBF800000BF800000ULL   // (-1.f, -1.f)
#define CBIAS    512.0f
#define CBIAS_PK 0x4400000044000000ULL   // (512.f, 512.f)

// ---------------------------------------------------------------------------
// Implicit-GEMM conv. 256 threads, microtile 4 rows x 4 cols (2 packed pairs).
// C[m,n] = sum_k U[m,k]*Wg[k,n] + bias[n],
//   U[m,k] = X[(m-10)*I + k] if k >= (10 - m%25)*I else 0.
// Product chain pr carried across 4 k-tiles (64 terms); biased FastTwoSum at
// every 4th tile and the last tile. pr reset to +0 packed (pure-pfma chains).
// Double-buffered smem with global prefetch (1 sync/tile).
// ---------------------------------------------------------------------------
template<int BM, int BN>
__global__ void __launch_bounds__(256)
conv_gemm_v14(const float* __restrict__ X, const float* __restrict__ Wg,
              const float* __restrict__ bias, float* __restrict__ Y,
              int N, int Nw, int Ktot, int I)
{
    constexpr int APASS = BM / 64;       // A-load row passes (256 thr, 1 float4 each)
    constexpr int CG    = BN / 4;        // col groups
    static_assert(256 / CG * 4 == BM, "compute map covers BM");
    __shared__ ull   As2[2][BM][18];     // dup (a,a); [row][kk]
    __shared__ float Bs[2][16][BN + 4];

    const int tid = threadIdx.x;
    const int bm = blockIdx.x * BM;
    const int bn = blockIdx.y * BN;

    // A-load geometry: rows arow + r*64, one float4 of k each
    const int arow = tid >> 2;          // 0..63
    const int akq  = (tid & 3) * 4;     // 0,4,8,12
    long abase[APASS];
    int  alow[APASS];
#pragma unroll
    for (int r = 0; r < APASS; r++) {
        int m = bm + arow + r * 64;
        int t = m % 25;
        abase[r] = (long)(m - 10) * I;
        alow[r]  = (t < 10) ? (10 - t) * I : 0;   // multiple of 4 (I%4==0)
    }
    // B-load geometry
    const int bkrow = tid / CG;          // k-row (guard <16)
    const int bcq   = (tid % CG) * 4;    // col offset

    ull acc[4][2], cmp[4][2], pr[4][2];  // [row q][col pair]
#pragma unroll
    for (int q = 0; q < 4; q++) {
        acc[q][0] = CBIAS_PK; acc[q][1] = CBIAS_PK;
        cmp[q][0] = 0ull;     cmp[q][1] = 0ull;
        pr[q][0]  = 0ull;     pr[q][1]  = 0ull;   // +0.0 packed
    }

    const int ty = tid / CG;            // 4-row group
    const int tx = tid % CG;            // 4-col group

    const int ntiles = (Ktot + 15) / 16;

    float4 va[APASS];
    float4 vb = make_float4(0.f, 0.f, 0.f, 0.f);

    auto load_tile = [&](int ti) {
        int k0 = ti * 16;
#pragma unroll
        for (int r = 0; r < APASS; r++) {
            int k = k0 + akq;
            va[r] = make_float4(0.f, 0.f, 0.f, 0.f);
            if (k >= alow[r] && k < Ktot)       // Ktot%4==0 -> vector-exact
                va[r] = *reinterpret_cast<const float4*>(X + abase[r] + k);
        }
        if (bkrow < 16) {
            int k = k0 + bkrow;
            vb = make_float4(0.f, 0.f, 0.f, 0.f);
            if (k < Ktot)
                vb = *reinterpret_cast<const float4*>(Wg + (size_t)k * Nw + bn + bcq);
        }
    };
    auto store_tile = [&](int buf) {
#pragma unroll
        for (int r = 0; r < APASS; r++) {
            int row = arow + r * 64;
            ulonglong2 w0; w0.x = pack2s(va[r].x); w0.y = pack2s(va[r].y);
            ulonglong2 w1; w1.x = pack2s(va[r].z); w1.y = pack2s(va[r].w);
            *reinterpret_cast<ulonglong2*>(&As2[buf][row][akq])     = w0;
            *reinterpret_cast<ulonglong2*>(&As2[buf][row][akq + 2]) = w1;
        }
        if (bkrow < 16)
            *reinterpret_cast<float4*>(&Bs[buf][bkrow][bcq]) = vb;
    };
    auto compute = [&](int buf, bool do_comp) {
#pragma unroll
        for (int kb = 0; kb < 16; kb += 4) {
            ull bq0[4], bq1[4];
#pragma unroll
            for (int kk = 0; kk < 4; kk++) {
                ulonglong2 bb = *reinterpret_cast<const ulonglong2*>(
                    &Bs[buf][kb + kk][tx * 4]);
                bq0[kk] = bb.x; bq1[kk] = bb.y;
            }
#pragma unroll
            for (int q = 0; q < 4; q++) {
                ull a[4];
#pragma unroll
                for (int kk = 0; kk < 4; kk += 2) {
                    ulonglong2 av = *reinterpret_cast<const ulonglong2*>(
                        &As2[buf][ty * 4 + q][kb + kk]);
                    a[kk] = av.x; a[kk + 1] = av.y;
                }
#pragma unroll
                for (int cp = 0; cp < 2; cp++) {
                    ull p = pr[q][cp];
#pragma unroll
                    for (int kk = 0; kk < 4; kk++)
                        p = pfma(a[kk], cp ? bq1[kk] : bq0[kk], p);
                    pr[q][cp] = p;
                }
            }
        }
        if (do_comp) {
#pragma unroll
            for (int q = 0; q < 4; q++) {
#pragma unroll
                for (int cp = 0; cp < 2; cp++) {
                    ull p = pr[q][cp];
                    ull s = acc[q][cp];
                    ull t = padd(s, p);
                    ull d = pfma(s, (ull)NEG1_PK, t);   // t - s  (exact)
                    ull e = pfma(d, (ull)NEG1_PK, p);   // p - d  (exact)
                    acc[q][cp] = t;
                    cmp[q][cp] = padd(cmp[q][cp], e);
                    pr[q][cp]  = 0ull;                  // restart chain at +0
                }
            }
        }
    };

    load_tile(0);
    store_tile(0);
    __syncthreads();
    for (int ti = 0; ti < ntiles; ti++) {
        bool more = (ti + 1 < ntiles);
        if (more) load_tile(ti + 1);            // overlap global latency with compute
        compute(ti & 1, ((ti & 3) == 3) || !more);
        if (more) {
            store_tile((ti + 1) & 1);
            __syncthreads();
        }
    }

#pragma unroll
    for (int q = 0; q < 4; q++) {
        int m = bm + ty * 4 + q;
#pragma unroll
        for (int cp = 0; cp < 2; cp++) {
            int n = bn + tx * 4 + cp * 2;
            float t0, t1, c0, c1;
            unpack2(acc[q][cp], t0, t1);
            unpack2(cmp[q][cp], c0, c1);
            if (n < N) {
                float v = __fadd_rn(__fsub_rn(t0, CBIAS), c0);
                Y[(size_t)m * N + n] = __fadd_rn(v, bias[n]);
            }
            if (n + 1 < N) {
                float v = __fadd_rn(__fsub_rn(t1, CBIAS), c1);
                Y[(size_t)m * N + n + 1] = __fadd_rn(v, bias[n + 1]);
            }
        }
    }
}

// ---------------------------------------------------------------------------
// LIF scan in fp64 (snntorch Leaky, reset='subtract'). Layout (B,T,C).
// ---------------------------------------------------------------------------
__global__ void lif_kernel(const float* __restrict__ Y, float* __restrict__ S, int C)
{
    int idx = blockIdx.x * blockDim.x + threadIdx.x;
    if (idx >= NB * C) return;
    int b = idx / C;
    int c = idx - b * C;
    const float* y = Y + (size_t)b * NT * C + c;
    float* s = S + (size_t)b * NT * C + c;
    double mem = 0.0;
#pragma unroll
    for (int t = 0; t < NT; t++) {
        double reset = (mem > 1.0) ? 1.0 : 0.0;
        mem = 0.95 * mem + (double)y[t * C] - reset;
        s[t * C] = (mem > 1.0) ? 1.0f : 0.0f;
    }
}

// Final LIF: layer-3 Y row stride 20. Emits spk3 (T,B,20) then mem3 (T,B,20).
__global__ void lif_out_kernel(const float* __restrict__ Y, float* __restrict__ out,
                               int out_size)
{
    int idx = blockIdx.x * blockDim.x + threadIdx.x;
    if (idx >= NB * 20) return;
    int b = idx / 20;
    int c = idx - b * 20;
    bool have_mem = (out_size >= 2 * NT * NB * 20);
    double mem = 0.0;
#pragma unroll
    for (int t = 0; t < NT; t++) {
        double reset = (mem > 1.0) ? 1.0 : 0.0;
        mem = 0.95 * mem + (double)Y[((size_t)b * NT + t) * 20 + c] - reset;
        float spk = (mem > 1.0) ? 1.0f : 0.0f;
        out[(size_t)t * NB * 20 + b * 20 + c] = spk;
        if (have_mem)
            out[(size_t)NT * NB * 20 + (size_t)t * NB * 20 + b * 20 + c] = (float)mem;
    }
}

// ---------------------------------------------------------------------------
extern "C" void kernel_launch(void* const* d_in, const int* in_sizes, int n_in,
                              void* d_out, int out_size)
{
    const float* data = (const float*)d_in[0];
    const float* W1   = (const float*)d_in[1];
    const float* b1   = (const float*)d_in[2];
    const float* P1   = (const float*)d_in[3];
    const float* SIG1 = (const float*)d_in[4];
    const float* g1   = (const float*)d_in[5];
    const float* be1  = (const float*)d_in[6];
    const float* mu1  = (const float*)d_in[7];
    const float* va1  = (const float*)d_in[8];
    const float* W2   = (const float*)d_in[9];
    const float* b2   = (const float*)d_in[10];
    const float* P2   = (const float*)d_in[11];
    const float* SIG2 = (const float*)d_in[12];
    const float* g2   = (const float*)d_in[13];
    const float* be2  = (const float*)d_in[14];
    const float* mu2  = (const float*)d_in[15];
    const float* va2  = (const float*)d_in[16];
    const float* W3   = (const float*)d_in[17];
    const float* b3   = (const float*)d_in[18];
    const float* P3   = (const float*)d_in[19];
    const float* SIG3 = (const float*)d_in[20];

    float *Wg1, *Wg2, *Wg3, *bb1, *bb2, *bb3, *Y, *S1, *S2, *Y3;
    cudaGetSymbolAddress((void**)&Wg1, g_Wg1);
    cudaGetSymbolAddress((void**)&Wg2, g_Wg2);
    cudaGetSymbolAddress((void**)&Wg3, g_Wg3);
    cudaGetSymbolAddress((void**)&bb1, g_bb1);
    cudaGetSymbolAddress((void**)&bb2, g_bb2);
    cudaGetSymbolAddress((void**)&bb3, g_bb3);
    cudaGetSymbolAddress((void**)&Y,   g_Y);
    cudaGetSymbolAddress((void**)&S1,  g_S1);
    cudaGetSymbolAddress((void**)&S2,  g_S2);
    cudaGetSymbolAddress((void**)&Y3,  g_Y3);

    // weight/bias prep (tiny). Layer-3 weights padded to 32 cols (zeros).
    zero_buf<<<(K2TOT * 32 + 255) / 256, 256>>>(Wg3, K2TOT * 32);
    prep_weights<<<(256 * 140 + 255) / 256, 256>>>(W1, P1, SIG1, g1, va1, Wg1, 256, 140, 256);
    prep_weights<<<(256 * 256 + 255) / 256, 256>>>(W2, P2, SIG2, g2, va2, Wg2, 256, 256, 256);
    prep_weights<<<(20 * 256 + 255) / 256, 256>>>(W3, P3, SIG3, nullptr, nullptr, Wg3, 20, 256, 32);
    prep_bias<<<1, 256>>>(b1, g1, be1, mu1, va1, bb1, 256);
    prep_bias<<<1, 256>>>(b2, g2, be2, mu2, va2, bb2, 256);
    prep_bias<<<1, 32>>>(b3, nullptr, nullptr, nullptr, nullptr, bb3, 20);

    // layer 1: dense inputs
    conv_gemm_v14<64, 64><<<dim3(400, 4), 256>>>(data, Wg1, bb1, Y, 256, 256, K1TOT, 140);
    lif_kernel<<<(NB * 256 + 255) / 256, 256>>>(Y, S1, 256);

    // layer 2: spike inputs
    conv_gemm_v14<64, 64><<<dim3(400, 4), 256>>>(S1, Wg2, bb2, Y, 256, 256, K2TOT, 256);
    lif_kernel<<<(NB * 256 + 255) / 256, 256>>>(Y, S2, 256);

    // layer 3: spike inputs, N=20 (weight rows padded to 32)
    conv_gemm_v14<128, 32><<<dim3(200, 1), 256>>>(S2, Wg3, bb3, Y3, 20, 32, K2TOT, 256);
    lif_out_kernel<<<(NB * 20 + 255) / 256, 256>>>(Y3, (float*)d_out, out_size);
}

// round 15
// speedup vs baseline: 1.6862x; 1.0332x over previous
#include <cuda_runtime.h>
#include <cstdint>

// SNN_Delay: 3x (DCLS gaussian 11-tap temporal conv -> [BN] -> LIF scan), forward only.
// Conv = implicit GEMM, biased FastTwoSum compensated accumulation on packed f32x2,
// product chains of 64 k-terms (comp every 2 BK32-tiles; same boundaries as R14).
// R15: BK=32 k-tiles via dynamic smem -> half the barriers, better tile amortization.
//      2 CTAs/SM retained (256 threads, ~110 regs).

typedef unsigned long long ull;

#define NT 25
#define NB 1024
#define MROWS (NB*NT)          // 25600
#define K1TOT (11*140)         // 1540
#define K2TOT (11*256)         // 2816

__device__ float g_Wg1[K1TOT*256];
__device__ float g_Wg2[K2TOT*256];
__device__ float g_Wg3[K2TOT*32];
__device__ float g_bb1[256];
__device__ float g_bb2[256];
__device__ float g_bb3[32];
__device__ float g_Y[MROWS*256];
__device__ float g_S1[MROWS*256];
__device__ float g_S2[MROWS*256];
__device__ float g_Y3[MROWS*20];

// ---------------------------------------------------------------------------
__global__ void prep_weights(const float* __restrict__ W, const float* __restrict__ P,
                             const float* __restrict__ SIG, const float* __restrict__ gamma,
                             const float* __restrict__ var, float* __restrict__ Wg,
                             int O, int I, int Ostride)
{
    int idx = blockIdx.x * blockDim.x + threadIdx.x;
    if (idx >= O * I) return;
    int o = idx / I;
    int i = idx - o * I;
    double pc = (double)P[idx] + 5.0;          // MAXD//2 = 5
    double s  = fabs((double)SIG[idx]) + 0.27;
    double g[11];
    double sum = 0.0;
#pragma unroll
    for (int j = 0; j < 11; j++) {
        double d = ((double)j - pc) / s;
        g[j] = exp(-0.5 * d * d);
        sum += g[j];
    }
    double scale = (double)W[idx] / (sum + 1e-7);
    if (gamma) scale *= (double)gamma[o] / sqrt((double)var[o] + 1e-5);
#pragma unroll
    for (int j = 0; j < 11; j++)
        Wg[(size_t)(j * I + i) * Ostride + o] = (float)(g[j] * scale);
}

__global__ void zero_buf(float* p, int n)
{
    int i = blockIdx.x * blockDim.x + threadIdx.x;
    if (i < n) p[i] = 0.f;
}

__global__ void prep_bias(const float* __restrict__ b, const float* __restrict__ gamma,
                          const float* __restrict__ beta, const float* __restrict__ mean,
                          const float* __restrict__ var, float* __restrict__ out, int O)
{
    int o = blockIdx.x * blockDim.x + threadIdx.x;
    if (o >= O) return;
    double v = (double)b[o];
    if (gamma) {
        double sc = (double)gamma[o] / sqrt((double)var[o] + 1e-5);
        v = (v - (double)mean[o]) * sc + (double)beta[o];
    }
    out[o] = (float)v;
}

// ---------------------------------------------------------------------------
// packed f32x2 helpers
// ---------------------------------------------------------------------------
__device__ __forceinline__ ull pack2s(float a) {
    ull r; asm("mov.b64 %0, {%1,%1};" : "=l"(r) : "f"(a)); return r;
}
__device__ __forceinline__ void unpack2(ull v, float& x, float& y) {
    asm("mov.b64 {%0,%1}, %2;" : "=f"(x), "=f"(y) : "l"(v));
}
__device__ __forceinline__ ull padd(ull a, ull b) {
    ull r; asm("add.rn.f32x2 %0, %1, %2;" : "=l"(r) : "l"(a), "l"(b)); return r;
}
__device__ __forceinline__ ull pfma(ull a, ull b, ull c) {
    ull r; asm("fma.rn.f32x2 %0, %1, %2, %3;" : "=l"(r) : "l"(a), "l"(b), "l"(c)); return r;
}

#define NEG1_PK  0xBF800000BF800000ULL   // (-1.f, -1.f)
#define CBIAS    512.0f
#define CBIAS_PK 0x4400000044000000ULL   // (512.f, 512.f)

// ---------------------------------------------------------------------------
// Implicit-GEMM conv. 256 threads, BK=32, microtile 4 rows x 4 cols.
// C[m,n] = sum_k U[m,k]*Wg[k,n] + bias[n],
//   U[m,k] = X[(m-10)*I + k] if k >= (10 - m%25)*I else 0.
// Product chain pr carried across 2 BK32-tiles (64 k-terms, boundaries at k=64*j,
// identical to R14); biased FastTwoSum at every 2nd tile and the last tile.
// Double-buffered dynamic smem with global prefetch (1 sync/tile).
// ---------------------------------------------------------------------------
template<int BM, int BN>
__global__ void __launch_bounds__(256)
conv_gemm_v15(const float* __restrict__ X, const float* __restrict__ Wg,
              const float* __restrict__ bias, float* __restrict__ Y,
              int N, int Nw, int Ktot, int I)
{
    constexpr int APASS = BM / 32;       // A-load row passes (256 thr, 1 float4 each)
    constexpr int CG    = BN / 4;        // col groups
    constexpr int BROWS = 256 / CG;      // B k-rows per pass
    constexpr int BPASS = 32 / BROWS;    // B-load passes
    static_assert(256 / CG * 4 == BM, "compute map covers BM");

    extern __shared__ char smem_raw[];
    typedef ull   AsT[BM][34];           // dup (a,a); [row][kk], 34 even -> 16B pairs
    typedef float BsT[32][BN + 4];
    AsT* As2 = reinterpret_cast<AsT*>(smem_raw);
    BsT* Bs  = reinterpret_cast<BsT*>(smem_raw + 2 * sizeof(AsT));

    const int tid = threadIdx.x;
    const int bm = blockIdx.x * BM;
    const int bn = blockIdx.y * BN;

    // A-load geometry: rows arow + r*32, one float4 of k each
    const int arow = tid >> 3;          // 0..31
    const int akq  = (tid & 7) * 4;     // 0..28
    long abase[APASS];
    int  alow[APASS];
#pragma unroll
    for (int r = 0; r < APASS; r++) {
        int m = bm + arow + r * 32;
        int t = m % 25;
        abase[r] = (long)(m - 10) * I;
        alow[r]  = (t < 10) ? (10 - t) * I : 0;   // multiple of 4 (I%4==0)
    }
    // B-load geometry
    const int bkrow = tid / CG;          // base k-row
    const int bcq   = (tid % CG) * 4;    // col offset

    ull acc[4][2], cmp[4][2], pr[4][2];  // [row q][col pair]
#pragma unroll
    for (int q = 0; q < 4; q++) {
        acc[q][0] = CBIAS_PK; acc[q][1] = CBIAS_PK;
        cmp[q][0] = 0ull;     cmp[q][1] = 0ull;
        pr[q][0]  = 0ull;     pr[q][1]  = 0ull;   // +0.0 packed
    }

    const int ty = tid / CG;            // 4-row group
    const int tx = tid % CG;            // 4-col group

    const int ntiles = (Ktot + 31) / 32;

    float4 va[APASS];
    float4 vb[BPASS];

    auto load_tile = [&](int ti) {
        int k0 = ti * 32;
#pragma unroll
        for (int r = 0; r < APASS; r++) {
            int k = k0 + akq;
            va[r] = make_float4(0.f, 0.f, 0.f, 0.f);
            if (k >= alow[r] && k < Ktot)       // Ktot%4==0 -> vector-exact
                va[r] = *reinterpret_cast<const float4*>(X + abase[r] + k);
        }
#pragma unroll
        for (int p = 0; p < BPASS; p++) {
            int krow = bkrow + p * BROWS;
            int k = k0 + krow;
            vb[p] = make_float4(0.f, 0.f, 0.f, 0.f);
            if (krow < 32 && k < Ktot)
                vb[p] = *reinterpret_cast<const float4*>(Wg + (size_t)k * Nw + bn + bcq);
        }
    };
    auto store_tile = [&](int buf) {
#pragma unroll
        for (int r = 0; r < APASS; r++) {
            int row = arow + r * 32;
            ulonglong2 w0; w0.x = pack2s(va[r].x); w0.y = pack2s(va[r].y);
            ulonglong2 w1; w1.x = pack2s(va[r].z); w1.y = pack2s(va[r].w);
            *reinterpret_cast<ulonglong2*>(&As2[buf][row][akq])     = w0;
            *reinterpret_cast<ulonglong2*>(&As2[buf][row][akq + 2]) = w1;
        }
#pragma unroll
        for (int p = 0; p < BPASS; p++) {
            int krow = bkrow + p * BROWS;
            if (krow < 32)
                *reinterpret_cast<float4*>(&Bs[buf][krow][bcq]) = vb[p];
        }
    };
    auto compute = [&](int buf, bool do_comp) {
#pragma unroll
        for (int kb = 0; kb < 32; kb += 4) {
            ull bq0[4], bq1[4];
#pragma unroll
            for (int kk = 0; kk < 4; kk++) {
                ulonglong2 bb = *reinterpret_cast<const ulonglong2*>(
                    &Bs[buf][kb + kk][tx * 4]);
                bq0[kk] = bb.x; bq1[kk] = bb.y;
            }
#pragma unroll
            for (int q = 0; q < 4; q++) {
                ull a[4];
#pragma unroll
                for (int kk = 0; kk < 4; kk += 2) {
                    ulonglong2 av = *reinterpret_cast<const ulonglong2*>(
                        &As2[buf][ty * 4 + q][kb + kk]);
                    a[kk] = av.x; a[kk + 1] = av.y;
                }
#pragma unroll
                for (int cp = 0; cp < 2; cp++) {
                    ull p = pr[q][cp];
#pragma unroll
                    for (int kk = 0; kk < 4; kk++)
                        p = pfma(a[kk], cp ? bq1[kk] : bq0[kk], p);
                    pr[q][cp] = p;
                }
            }
        }
        if (do_comp) {
#pragma unroll
            for (int q = 0; q < 4; q++) {
#pragma unroll
                for (int cp = 0; cp < 2; cp++) {
                    ull p = pr[q][cp];
                    ull s = acc[q][cp];
                    ull t = padd(s, p);
                    ull d = pfma(s, (ull)NEG1_PK, t);   // t - s  (exact)
                    ull e = pfma(d, (ull)NEG1_PK, p);   // p - d  (exact)
                    acc[q][cp] = t;
                    cmp[q][cp] = padd(cmp[q][cp], e);
                    pr[q][cp]  = 0ull;                  // restart chain at +0
                }
            }
        }
    };

    load_tile(0);
    store_tile(0);
    __syncthreads();
    for (int ti = 0; ti < ntiles; ti++) {
        bool more = (ti + 1 < ntiles);
        if (more) load_tile(ti + 1);            // overlap global latency with compute
        compute(ti & 1, ((ti & 1) == 1) || !more);
        if (more) {
            store_tile((ti + 1) & 1);
            __syncthreads();
        }
    }

#pragma unroll
    for (int q = 0; q < 4; q++) {
        int m = bm + ty * 4 + q;
#pragma unroll
        for (int cp = 0; cp < 2; cp++) {
            int n = bn + tx * 4 + cp * 2;
            float t0, t1, c0, c1;
            unpack2(acc[q][cp], t0, t1);
            unpack2(cmp[q][cp], c0, c1);
            if (n < N) {
                float v = __fadd_rn(__fsub_rn(t0, CBIAS), c0);
                Y[(size_t)m * N + n] = __fadd_rn(v, bias[n]);
            }
            if (n + 1 < N) {
                float v = __fadd_rn(__fsub_rn(t1, CBIAS), c1);
                Y[(size_t)m * N + n + 1] = __fadd_rn(v, bias[n + 1]);
            }
        }
    }
}

// ---------------------------------------------------------------------------
// LIF scan in fp64 (snntorch Leaky, reset='subtract'). Layout (B,T,C).
// ---------------------------------------------------------------------------
__global__ void lif_kernel(const float* __restrict__ Y, float* __restrict__ S, int C)
{
    int idx = blockIdx.x * blockDim.x + threadIdx.x;
    if (idx >= NB * C) return;
    int b = idx / C;
    int c = idx - b * C;
    const float* y = Y + (size_t)b * NT * C + c;
    float* s = S + (size_t)b * NT * C + c;
    double mem = 0.0;
#pragma unroll
    for (int t = 0; t < NT; t++) {
        double reset = (mem > 1.0) ? 1.0 : 0.0;
        mem = 0.95 * mem + (double)y[t * C] - reset;
        s[t * C] = (mem > 1.0) ? 1.0f : 0.0f;
    }
}

// Final LIF: layer-3 Y row stride 20. Emits spk3 (T,B,20) then mem3 (T,B,20).
__global__ void lif_out_kernel(const float* __restrict__ Y, float* __restrict__ out,
                               int out_size)
{
    int idx = blockIdx.x * blockDim.x + threadIdx.x;
    if (idx >= NB * 20) return;
    int b = idx / 20;
    int c = idx - b * 20;
    bool have_mem = (out_size >= 2 * NT * NB * 20);
    double mem = 0.0;
#pragma unroll
    for (int t = 0; t < NT; t++) {
        double reset = (mem > 1.0) ? 1.0 : 0.0;
        mem = 0.95 * mem + (double)Y[((size_t)b * NT + t) * 20 + c] - reset;
        float spk = (mem > 1.0) ? 1.0f : 0.0f;
        out[(size_t)t * NB * 20 + b * 20 + c] = spk;
        if (have_mem)
            out[(size_t)NT * NB * 20 + (size_t)t * NB * 20 + b * 20 + c] = (float)mem;
    }
}

// ---------------------------------------------------------------------------
extern "C" void kernel_launch(void* const* d_in, const int* in_sizes, int n_in,
                              void* d_out, int out_size)
{
    const float* data = (const float*)d_in[0];
    const float* W1   = (const float*)d_in[1];
    const float* b1   = (const float*)d_in[2];
    const float* P1   = (const float*)d_in[3];
    const float* SIG1 = (const float*)d_in[4];
    const float* g1   = (const float*)d_in[5];
    const float* be1  = (const float*)d_in[6];
    const float* mu1  = (const float*)d_in[7];
    const float* va1  = (const float*)d_in[8];
    const float* W2   = (const float*)d_in[9];
    const float* b2   = (const float*)d_in[10];
    const float* P2   = (const float*)d_in[11];
    const float* SIG2 = (const float*)d_in[12];
    const float* g2   = (const float*)d_in[13];
    const float* be2  = (const float*)d_in[14];
    const float* mu2  = (const float*)d_in[15];
    const float* va2  = (const float*)d_in[16];
    const float* W3   = (const float*)d_in[17];
    const float* b3   = (const float*)d_in[18];
    const float* P3   = (const float*)d_in[19];
    const float* SIG3 = (const float*)d_in[20];

    float *Wg1, *Wg2, *Wg3, *bb1, *bb2, *bb3, *Y, *S1, *S2, *Y3;
    cudaGetSymbolAddress((void**)&Wg1, g_Wg1);
    cudaGetSymbolAddress((void**)&Wg2, g_Wg2);
    cudaGetSymbolAddress((void**)&Wg3, g_Wg3);
    cudaGetSymbolAddress((void**)&bb1, g_bb1);
    cudaGetSymbolAddress((void**)&bb2, g_bb2);
    cudaGetSymbolAddress((void**)&bb3, g_bb3);
    cudaGetSymbolAddress((void**)&Y,   g_Y);
    cudaGetSymbolAddress((void**)&S1,  g_S1);
    cudaGetSymbolAddress((void**)&S2,  g_S2);
    cudaGetSymbolAddress((void**)&Y3,  g_Y3);

    // dynamic smem sizes
    const int SMEM_64_64  = 2 * 64  * 34 * 8 + 2 * 32 * 68 * 4;  // 34816+17408=52224
    const int SMEM_128_32 = 2 * 128 * 34 * 8 + 2 * 32 * 36 * 4;  // 69632+9216 =78848
    cudaFuncSetAttribute(conv_gemm_v15<64, 64>,
                         cudaFuncAttributeMaxDynamicSharedMemorySize, SMEM_64_64);
    cudaFuncSetAttribute(conv_gemm_v15<128, 32>,
                         cudaFuncAttributeMaxDynamicSharedMemorySize, SMEM_128_32);

    // weight/bias prep (tiny). Layer-3 weights padded to 32 cols (zeros).
    zero_buf<<<(K2TOT * 32 + 255) / 256, 256>>>(Wg3, K2TOT * 32);
    prep_weights<<<(256 * 140 + 255) / 256, 256>>>(W1, P1, SIG1, g1, va1, Wg1, 256, 140, 256);
    prep_weights<<<(256 * 256 + 255) / 256, 256>>>(W2, P2, SIG2, g2, va2, Wg2, 256, 256, 256);
    prep_weights<<<(20 * 256 + 255) / 256, 256>>>(W3, P3, SIG3, nullptr, nullptr, Wg3, 20, 256, 32);
    prep_bias<<<1, 256>>>(b1, g1, be1, mu1, va1, bb1, 256);
    prep_bias<<<1, 256>>>(b2, g2, be2, mu2, va2, bb2, 256);
    prep_bias<<<1, 32>>>(b3, nullptr, nullptr, nullptr, nullptr, bb3, 20);

    // layer 1: dense inputs
    conv_gemm_v15<64, 64><<<dim3(400, 4), 256, SMEM_64_64>>>(data, Wg1, bb1, Y, 256, 256, K1TOT, 140);
    lif_kernel<<<(NB * 256 + 255) / 256, 256>>>(Y, S1, 256);

    // layer 2: spike inputs
    conv_gemm_v15<64, 64><<<dim3(400, 4), 256, SMEM_64_64>>>(S1, Wg2, bb2, Y, 256, 256, K2TOT, 256);
    lif_kernel<<<(NB * 256 + 255) / 256, 256>>>(Y, S2, 256);

    // layer 3: spike inputs, N=20 (weight rows padded to 32)
    conv_gemm_v15<128, 32><<<dim3(200, 1), 256, SMEM_128_32>>>(S2, Wg3, bb3, Y3, 20, 32, K2TOT, 256);
    lif_out_kernel<<<(NB * 20 + 255) / 256, 256>>>(Y3, (float*)d_out, out_size);
}

// round 16
// speedup vs baseline: 1.6905x; 1.0026x over previous
#include <cuda_runtime.h>
#include <cstdint>

// SNN_Delay: 3x (DCLS gaussian 11-tap temporal conv -> [BN] -> LIF scan), forward only.
// Conv = implicit GEMM, biased FastTwoSum compensated accumulation on packed f32x2,
// product chains of 128 k-terms (comp every 4 BK32-tiles).
// R16: compensation frequency halved vs R15 (chains 64 -> 128 terms); everything
//      else identical (BK=32 double-buffered dynamic smem, 2x 256-thread CTAs/SM).

typedef unsigned long long ull;

#define NT 25
#define NB 1024
#define MROWS (NB*NT)          // 25600
#define K1TOT (11*140)         // 1540
#define K2TOT (11*256)         // 2816

__device__ float g_Wg1[K1TOT*256];
__device__ float g_Wg2[K2TOT*256];
__device__ float g_Wg3[K2TOT*32];
__device__ float g_bb1[256];
__device__ float g_bb2[256];
__device__ float g_bb3[32];
__device__ float g_Y[MROWS*256];
__device__ float g_S1[MROWS*256];
__device__ float g_S2[MROWS*256];
__device__ float g_Y3[MROWS*20];

// ---------------------------------------------------------------------------
__global__ void prep_weights(const float* __restrict__ W, const float* __restrict__ P,
                             const float* __restrict__ SIG, const float* __restrict__ gamma,
                             const float* __restrict__ var, float* __restrict__ Wg,
                             int O, int I, int Ostride)
{
    int idx = blockIdx.x * blockDim.x + threadIdx.x;
    if (idx >= O * I) return;
    int o = idx / I;
    int i = idx - o * I;
    double pc = (double)P[idx] + 5.0;          // MAXD//2 = 5
    double s  = fabs((double)SIG[idx]) + 0.27;
    double g[11];
    double sum = 0.0;
#pragma unroll
    for (int j = 0; j < 11; j++) {
        double d = ((double)j - pc) / s;
        g[j] = exp(-0.5 * d * d);
        sum += g[j];
    }
    double scale = (double)W[idx] / (sum + 1e-7);
    if (gamma) scale *= (double)gamma[o] / sqrt((double)var[o] + 1e-5);
#pragma unroll
    for (int j = 0; j < 11; j++)
        Wg[(size_t)(j * I + i) * Ostride + o] = (float)(g[j] * scale);
}

__global__ void zero_buf(float* p, int n)
{
    int i = blockIdx.x * blockDim.x + threadIdx.x;
    if (i < n) p[i] = 0.f;
}

__global__ void prep_bias(const float* __restrict__ b, const float* __restrict__ gamma,
                          const float* __restrict__ beta, const float* __restrict__ mean,
                          const float* __restrict__ var, float* __restrict__ out, int O)
{
    int o = blockIdx.x * blockDim.x + threadIdx.x;
    if (o >= O) return;
    double v = (double)b[o];
    if (gamma) {
        double sc = (double)gamma[o] / sqrt((double)var[o] + 1e-5);
        v = (v - (double)mean[o]) * sc + (double)beta[o];
    }
    out[o] = (float)v;
}

// ---------------------------------------------------------------------------
// packed f32x2 helpers
// ---------------------------------------------------------------------------
__device__ __forceinline__ ull pack2s(float a) {
    ull r; asm("mov.b64 %0, {%1,%1};" : "=l"(r) : "f"(a)); return r;
}
__device__ __forceinline__ void unpack2(ull v, float& x, float& y) {
    asm("mov.b64 {%0,%1}, %2;" : "=f"(x), "=f"(y) : "l"(v));
}
__device__ __forceinline__ ull padd(ull a, ull b) {
    ull r; asm("add.rn.f32x2 %0, %1, %2;" : "=l"(r) : "l"(a), "l"(b)); return r;
}
__device__ __forceinline__ ull pfma(ull a, ull b, ull c) {
    ull r; asm("fma.rn.f32x2 %0, %1, %2, %3;" : "=l"(r) : "l"(a), "l"(b), "l"(c)); return r;
}

#define NEG1_PK  0xBF800000BF800000ULL   // (-1.f, -1.f)
#define CBIAS    512.0f
#define CBIAS_PK 0x4400000044000000ULL   // (512.f, 512.f)

// ---------------------------------------------------------------------------
// Implicit-GEMM conv. 256 threads, BK=32, microtile 4 rows x 4 cols.
// C[m,n] = sum_k U[m,k]*Wg[k,n] + bias[n],
//   U[m,k] = X[(m-10)*I + k] if k >= (10 - m%25)*I else 0.
// Product chain pr carried across 4 BK32-tiles (128 k-terms); biased FastTwoSum
// at every 4th tile and the last tile. pr reset to +0 packed (pure-pfma chains).
// Double-buffered dynamic smem with global prefetch (1 sync/tile).
// ---------------------------------------------------------------------------
template<int BM, int BN>
__global__ void __launch_bounds__(256)
conv_gemm_v16(const float* __restrict__ X, const float* __restrict__ Wg,
              const float* __restrict__ bias, float* __restrict__ Y,
              int N, int Nw, int Ktot, int I)
{
    constexpr int APASS = BM / 32;       // A-load row passes (256 thr, 1 float4 each)
    constexpr int CG    = BN / 4;        // col groups
    constexpr int BROWS = 256 / CG;      // B k-rows per pass
    constexpr int BPASS = 32 / BROWS;    // B-load passes
    static_assert(256 / CG * 4 == BM, "compute map covers BM");

    extern __shared__ char smem_raw[];
    typedef ull   AsT[BM][34];           // dup (a,a); [row][kk], 34 even -> 16B pairs
    typedef float BsT[32][BN + 4];
    AsT* As2 = reinterpret_cast<AsT*>(smem_raw);
    BsT* Bs  = reinterpret_cast<BsT*>(smem_raw + 2 * sizeof(AsT));

    const int tid = threadIdx.x;
    const int bm = blockIdx.x * BM;
    const int bn = blockIdx.y * BN;

    // A-load geometry: rows arow + r*32, one float4 of k each
    const int arow = tid >> 3;          // 0..31
    const int akq  = (tid & 7) * 4;     // 0..28
    long abase[APASS];
    int  alow[APASS];
#pragma unroll
    for (int r = 0; r < APASS; r++) {
        int m = bm + arow + r * 32;
        int t = m % 25;
        abase[r] = (long)(m - 10) * I;
        alow[r]  = (t < 10) ? (10 - t) * I : 0;   // multiple of 4 (I%4==0)
    }
    // B-load geometry
    const int bkrow = tid / CG;          // base k-row
    const int bcq   = (tid % CG) * 4;    // col offset

    ull acc[4][2], cmp[4][2], pr[4][2];  // [row q][col pair]
#pragma unroll
    for (int q = 0; q < 4; q++) {
        acc[q][0] = CBIAS_PK; acc[q][1] = CBIAS_PK;
        cmp[q][0] = 0ull;     cmp[q][1] = 0ull;
        pr[q][0]  = 0ull;     pr[q][1]  = 0ull;   // +0.0 packed
    }

    const int ty = tid / CG;            // 4-row group
    const int tx = tid % CG;            // 4-col group

    const int ntiles = (Ktot + 31) / 32;

    float4 va[APASS];
    float4 vb[BPASS];

    auto load_tile = [&](int ti) {
        int k0 = ti * 32;
#pragma unroll
        for (int r = 0; r < APASS; r++) {
            int k = k0 + akq;
            va[r] = make_float4(0.f, 0.f, 0.f, 0.f);
            if (k >= alow[r] && k < Ktot)       // Ktot%4==0 -> vector-exact
                va[r] = *reinterpret_cast<const float4*>(X + abase[r] + k);
        }
#pragma unroll
        for (int p = 0; p < BPASS; p++) {
            int krow = bkrow + p * BROWS;
            int k = k0 + krow;
            vb[p] = make_float4(0.f, 0.f, 0.f, 0.f);
            if (krow < 32 && k < Ktot)
                vb[p] = *reinterpret_cast<const float4*>(Wg + (size_t)k * Nw + bn + bcq);
        }
    };
    auto store_tile = [&](int buf) {
#pragma unroll
        for (int r = 0; r < APASS; r++) {
            int row = arow + r * 32;
            ulonglong2 w0; w0.x = pack2s(va[r].x); w0.y = pack2s(va[r].y);
            ulonglong2 w1; w1.x = pack2s(va[r].z); w1.y = pack2s(va[r].w);
            *reinterpret_cast<ulonglong2*>(&As2[buf][row][akq])     = w0;
            *reinterpret_cast<ulonglong2*>(&As2[buf][row][akq + 2]) = w1;
        }
#pragma unroll
        for (int p = 0; p < BPASS; p++) {
            int krow = bkrow + p * BROWS;
            if (krow < 32)
                *reinterpret_cast<float4*>(&Bs[buf][krow][bcq]) = vb[p];
        }
    };
    auto compute = [&](int buf, bool do_comp) {
#pragma unroll
        for (int kb = 0; kb < 32; kb += 4) {
            ull bq0[4], bq1[4];
#pragma unroll
            for (int kk = 0; kk < 4; kk++) {
                ulonglong2 bb = *reinterpret_cast<const ulonglong2*>(
                    &Bs[buf][kb + kk][tx * 4]);
                bq0[kk] = bb.x; bq1[kk] = bb.y;
            }
#pragma unroll
            for (int q = 0; q < 4; q++) {
                ull a[4];
#pragma unroll
                for (int kk = 0; kk < 4; kk += 2) {
                    ulonglong2 av = *reinterpret_cast<const ulonglong2*>(
                        &As2[buf][ty * 4 + q][kb + kk]);
                    a[kk] = av.x; a[kk + 1] = av.y;
                }
#pragma unroll
                for (int cp = 0; cp < 2; cp++) {
                    ull p = pr[q][cp];
#pragma unroll
                    for (int kk = 0; kk < 4; kk++)
                        p = pfma(a[kk], cp ? bq1[kk] : bq0[kk], p);
                    pr[q][cp] = p;
                }
            }
        }
        if (do_comp) {
#pragma unroll
            for (int q = 0; q < 4; q++) {
#pragma unroll
                for (int cp = 0; cp < 2; cp++) {
                    ull p = pr[q][cp];
                    ull s = acc[q][cp];
                    ull t = padd(s, p);
                    ull d = pfma(s, (ull)NEG1_PK, t);   // t - s  (exact)
                    ull e = pfma(d, (ull)NEG1_PK, p);   // p - d  (exact)
                    acc[q][cp] = t;
                    cmp[q][cp] = padd(cmp[q][cp], e);
                    pr[q][cp]  = 0ull;                  // restart chain at +0
                }
            }
        }
    };

    load_tile(0);
    store_tile(0);
    __syncthreads();
    for (int ti = 0; ti < ntiles; ti++) {
        bool more = (ti + 1 < ntiles);
        if (more) load_tile(ti + 1);            // overlap global latency with compute
        compute(ti & 1, ((ti & 3) == 3) || !more);
        if (more) {
            store_tile((ti + 1) & 1);
            __syncthreads();
        }
    }

#pragma unroll
    for (int q = 0; q < 4; q++) {
        int m = bm + ty * 4 + q;
#pragma unroll
        for (int cp = 0; cp < 2; cp++) {
            int n = bn + tx * 4 + cp * 2;
            float t0, t1, c0, c1;
            unpack2(acc[q][cp], t0, t1);
            unpack2(cmp[q][cp], c0, c1);
            if (n < N) {
                float v = __fadd_rn(__fsub_rn(t0, CBIAS), c0);
                Y[(size_t)m * N + n] = __fadd_rn(v, bias[n]);
            }
            if (n + 1 < N) {
                float v = __fadd_rn(__fsub_rn(t1, CBIAS), c1);
                Y[(size_t)m * N + n + 1] = __fadd_rn(v, bias[n + 1]);
            }
        }
    }
}

// ---------------------------------------------------------------------------
// LIF scan in fp64 (snntorch Leaky, reset='subtract'). Layout (B,T,C).
// ---------------------------------------------------------------------------
__global__ void lif_kernel(const float* __restrict__ Y, float* __restrict__ S, int C)
{
    int idx = blockIdx.x * blockDim.x + threadIdx.x;
    if (idx >= NB * C) return;
    int b = idx / C;
    int c = idx - b * C;
    const float* y = Y + (size_t)b * NT * C + c;
    float* s = S + (size_t)b * NT * C + c;
    double mem = 0.0;
#pragma unroll
    for (int t = 0; t < NT; t++) {
        double reset = (mem > 1.0) ? 1.0 : 0.0;
        mem = 0.95 * mem + (double)y[t * C] - reset;
        s[t * C] = (mem > 1.0) ? 1.0f : 0.0f;
    }
}

// Final LIF: layer-3 Y row stride 20. Emits spk3 (T,B,20) then mem3 (T,B,20).
__global__ void lif_out_kernel(const float* __restrict__ Y, float* __restrict__ out,
                               int out_size)
{
    int idx = blockIdx.x * blockDim.x + threadIdx.x;
    if (idx >= NB * 20) return;
    int b = idx / 20;
    int c = idx - b * 20;
    bool have_mem = (out_size >= 2 * NT * NB * 20);
    double mem = 0.0;
#pragma unroll
    for (int t = 0; t < NT; t++) {
        double reset = (mem > 1.0) ? 1.0 : 0.0;
        mem = 0.95 * mem + (double)Y[((size_t)b * NT + t) * 20 + c] - reset;
        float spk = (mem > 1.0) ? 1.0f : 0.0f;
        out[(size_t)t * NB * 20 + b * 20 + c] = spk;
        if (have_mem)
            out[(size_t)NT * NB * 20 + (size_t)t * NB * 20 + b * 20 + c] = (float)mem;
    }
}

// ---------------------------------------------------------------------------
extern "C" void kernel_launch(void* const* d_in, const int* in_sizes, int n_in,
                              void* d_out, int out_size)
{
    const float* data = (const float*)d_in[0];
    const float* W1   = (const float*)d_in[1];
    const float* b1   = (const float*)d_in[2];
    const float* P1   = (const float*)d_in[3];
    const float* SIG1 = (const float*)d_in[4];
    const float* g1   = (const float*)d_in[5];
    const float* be1  = (const float*)d_in[6];
    const float* mu1  = (const float*)d_in[7];
    const float* va1  = (const float*)d_in[8];
    const float* W2   = (const float*)d_in[9];
    const float* b2   = (const float*)d_in[10];
    const float* P2   = (const float*)d_in[11];
    const float* SIG2 = (const float*)d_in[12];
    const float* g2   = (const float*)d_in[13];
    const float* be2  = (const float*)d_in[14];
    const float* mu2  = (const float*)d_in[15];
    const float* va2  = (const float*)d_in[16];
    const float* W3   = (const float*)d_in[17];
    const float* b3   = (const float*)d_in[18];
    const float* P3   = (const float*)d_in[19];
    const float* SIG3 = (const float*)d_in[20];

    float *Wg1, *Wg2, *Wg3, *bb1, *bb2, *bb3, *Y, *S1, *S2, *Y3;
    cudaGetSymbolAddress((void**)&Wg1, g_Wg1);
    cudaGetSymbolAddress((void**)&Wg2, g_Wg2);
    cudaGetSymbolAddress((void**)&Wg3, g_Wg3);
    cudaGetSymbolAddress((void**)&bb1, g_bb1);
    cudaGetSymbolAddress((void**)&bb2, g_bb2);
    cudaGetSymbolAddress((void**)&bb3, g_bb3);
    cudaGetSymbolAddress((void**)&Y,   g_Y);
    cudaGetSymbolAddress((void**)&S1,  g_S1);
    cudaGetSymbolAddress((void**)&S2,  g_S2);
    cudaGetSymbolAddress((void**)&Y3,  g_Y3);

    // dynamic smem sizes
    const int SMEM_64_64  = 2 * 64  * 34 * 8 + 2 * 32 * 68 * 4;  // 52224
    const int SMEM_128_32 = 2 * 128 * 34 * 8 + 2 * 32 * 36 * 4;  // 78848
    cudaFuncSetAttribute(conv_gemm_v16<64, 64>,
                         cudaFuncAttributeMaxDynamicSharedMemorySize, SMEM_64_64);
    cudaFuncSetAttribute(conv_gemm_v16<128, 32>,
                         cudaFuncAttributeMaxDynamicSharedMemorySize, SMEM_128_32);

    // weight/bias prep (tiny). Layer-3 weights padded to 32 cols (zeros).
    zero_buf<<<(K2TOT * 32 + 255) / 256, 256>>>(Wg3, K2TOT * 32);
    prep_weights<<<(256 * 140 + 255) / 256, 256>>>(W1, P1, SIG1, g1, va1, Wg1, 256, 140, 256);
    prep_weights<<<(256 * 256 + 255) / 256, 256>>>(W2, P2, SIG2, g2, va2, Wg2, 256, 256, 256);
    prep_weights<<<(20 * 256 + 255) / 256, 256>>>(W3, P3, SIG3, nullptr, nullptr, Wg3, 20, 256, 32);
    prep_bias<<<1, 256>>>(b1, g1, be1, mu1, va1, bb1, 256);
    prep_bias<<<1, 256>>>(b2, g2, be2, mu2, va2, bb2, 256);
    prep_bias<<<1, 32>>>(b3, nullptr, nullptr, nullptr, nullptr, bb3, 20);

    // layer 1: dense inputs
    conv_gemm_v16<64, 64><<<dim3(400, 4), 256, SMEM_64_64>>>(data, Wg1, bb1, Y, 256, 256, K1TOT, 140);
    lif_kernel<<<(NB * 256 + 255) / 256, 256>>>(Y, S1, 256);

    // layer 2: spike inputs
    conv_gemm_v16<64, 64><<<dim3(400, 4), 256, SMEM_64_64>>>(S1, Wg2, bb2, Y, 256, 256, K2TOT, 256);
    lif_kernel<<<(NB * 256 + 255) / 256, 256>>>(Y, S2, 256);

    // layer 3: spike inputs, N=20 (weight rows padded to 32)
    conv_gemm_v16<128, 32><<<dim3(200, 1), 256, SMEM_128_32>>>(S2, Wg3, bb3, Y3, 20, 32, K2TOT, 256);
    lif_out_kernel<<<(NB * 20 + 255) / 256, 256>>>(Y3, (float*)d_out, out_size);
}